// round 12
// baseline (speedup 1.0000x reference)
#include <cuda_runtime.h>
#include <cuda_bf16.h>
#include <math.h>
#include <stdint.h>

#define S_LEN 2048
#define HID   2048
#define NH    8
#define NKV   4
#define HD    256
#define QSCALE 0.0625f       // D^-0.5
#define INV_CAP 0.02f        // 1/50
#define CAP    50.0f

// ---- fp32 scratch ----
__device__ float g_qkv[(size_t)4096 * 4096];   // q cols 0-2047 | k 2048-3071 | v 3072-4095
__device__ float g_linv[32768];

// ---- bf16 split scratch ----
__device__ uint4 g_hs_h[(size_t)4096 * 2048 / 8];
__device__ uint4 g_hs_l[(size_t)4096 * 2048 / 8];
__device__ uint4 g_att_h[(size_t)4096 * 2048 / 8];
__device__ uint4 g_att_l[(size_t)4096 * 2048 / 8];
__device__ uint4 g_w_h[(size_t)4096 * 2048 / 8];   // wq rows 0-2047 | wk | wv
__device__ uint4 g_w_l[(size_t)4096 * 2048 / 8];
__device__ uint4 g_wo_h[(size_t)2048 * 2048 / 8];
__device__ uint4 g_wo_l[(size_t)2048 * 2048 / 8];
__device__ uint4 g_qh[(size_t)4096 * 2048 / 8];
__device__ uint4 g_ql[(size_t)4096 * 2048 / 8];
__device__ uint4 g_kh[(size_t)4096 * 1024 / 8];
__device__ uint4 g_kl[(size_t)4096 * 1024 / 8];
__device__ uint4 g_vh[(size_t)4096 * 1024 / 8];
__device__ uint4 g_vl[(size_t)4096 * 1024 / 8];

// =====================================================================
// helpers
// =====================================================================
__device__ __forceinline__ uint32_t smem_u32(const void* p) {
    uint32_t a;
    asm("{ .reg .u64 t; cvta.to.shared.u64 t, %1; cvt.u32.u64 %0, t; }"
        : "=r"(a) : "l"(p));
    return a;
}
__device__ __forceinline__ void cp_async16(uint32_t saddr, const void* gaddr) {
    asm volatile("cp.async.cg.shared.global [%0], [%1], 16;"
                 :: "r"(saddr), "l"(gaddr) : "memory");
}
#define CP_COMMIT() asm volatile("cp.async.commit_group;" ::: "memory")
#define CP_WAIT1()  asm volatile("cp.async.wait_group 1;" ::: "memory")
#define CP_WAIT0()  asm volatile("cp.async.wait_group 0;" ::: "memory")

__device__ __forceinline__ void ldsm_x4(uint32_t* r, uint32_t addr) {
    asm volatile("ldmatrix.sync.aligned.m8n8.x4.shared.b16 {%0,%1,%2,%3}, [%4];"
                 : "=r"(r[0]), "=r"(r[1]), "=r"(r[2]), "=r"(r[3]) : "r"(addr));
}
__device__ __forceinline__ void ldsm_x4t(uint32_t* r, uint32_t addr) {
    asm volatile("ldmatrix.sync.aligned.m8n8.x4.trans.shared.b16 {%0,%1,%2,%3}, [%4];"
                 : "=r"(r[0]), "=r"(r[1]), "=r"(r[2]), "=r"(r[3]) : "r"(addr));
}
__device__ __forceinline__ void mma16816(float* c, const uint32_t* a,
                                         const uint32_t* b) {
    asm volatile(
        "mma.sync.aligned.m16n8k16.row.col.f32.bf16.bf16.f32 "
        "{%0,%1,%2,%3}, {%4,%5,%6,%7}, {%8,%9}, {%0,%1,%2,%3};"
        : "+f"(c[0]), "+f"(c[1]), "+f"(c[2]), "+f"(c[3])
        : "r"(a[0]), "r"(a[1]), "r"(a[2]), "r"(a[3]), "r"(b[0]), "r"(b[1]));
}
// B passed as two scalar regs (for merged x4 B loads: mats {0,2} / {1,3})
__device__ __forceinline__ void mma16816s(float* c, const uint32_t* a,
                                          uint32_t b0, uint32_t b1) {
    asm volatile(
        "mma.sync.aligned.m16n8k16.row.col.f32.bf16.bf16.f32 "
        "{%0,%1,%2,%3}, {%4,%5,%6,%7}, {%8,%9}, {%0,%1,%2,%3};"
        : "+f"(c[0]), "+f"(c[1]), "+f"(c[2]), "+f"(c[3])
        : "r"(a[0]), "r"(a[1]), "r"(a[2]), "r"(a[3]), "r"(b0), "r"(b1));
}

// =====================================================================
// split fp32 -> (hi, lo) bf16  (contiguous)
// =====================================================================
__global__ void split_kernel(const float* __restrict__ x,
                             __nv_bfloat16* __restrict__ hi,
                             __nv_bfloat16* __restrict__ lo, int n4)
{
    int i = blockIdx.x * blockDim.x + threadIdx.x;
    if (i >= n4) return;
    float4 v = ((const float4*)x)[i];
    __nv_bfloat16 h0 = __float2bfloat16(v.x);
    __nv_bfloat16 h1 = __float2bfloat16(v.y);
    __nv_bfloat16 h2 = __float2bfloat16(v.z);
    __nv_bfloat16 h3 = __float2bfloat16(v.w);
    __nv_bfloat16 l0 = __float2bfloat16(v.x - __bfloat162float(h0));
    __nv_bfloat16 l1 = __float2bfloat16(v.y - __bfloat162float(h1));
    __nv_bfloat16 l2 = __float2bfloat16(v.z - __bfloat162float(h2));
    __nv_bfloat16 l3 = __float2bfloat16(v.w - __bfloat162float(h3));
    __nv_bfloat162* h2p = (__nv_bfloat162*)hi;
    __nv_bfloat162* l2p = (__nv_bfloat162*)lo;
    h2p[2 * i]     = __halves2bfloat162(h0, h1);
    h2p[2 * i + 1] = __halves2bfloat162(h2, h3);
    l2p[2 * i]     = __halves2bfloat162(l0, l1);
    l2p[2 * i + 1] = __halves2bfloat162(l2, l3);
}

// =====================================================================
// split fp32 submatrix (row stride 4096, col offset) -> bf16 hi/lo [., 1024]
// =====================================================================
__global__ void split_strided_kernel(const float* __restrict__ x, int coloff,
                                     __nv_bfloat16* __restrict__ hi,
                                     __nv_bfloat16* __restrict__ lo)
{
    int i = blockIdx.x * blockDim.x + threadIdx.x;
    if (i >= 4096 * 256) return;
    int row = i >> 8, c4 = (i & 255) << 2;
    float4 v = *(const float4*)(x + (size_t)row * 4096 + coloff + c4);
    __nv_bfloat16 h0 = __float2bfloat16(v.x);
    __nv_bfloat16 h1 = __float2bfloat16(v.y);
    __nv_bfloat16 h2 = __float2bfloat16(v.z);
    __nv_bfloat16 h3 = __float2bfloat16(v.w);
    size_t o = (size_t)row * 1024 + c4;
    *(__nv_bfloat162*)(hi + o)     = __halves2bfloat162(h0, h1);
    *(__nv_bfloat162*)(hi + o + 2) = __halves2bfloat162(h2, h3);
    *(__nv_bfloat162*)(lo + o)     = __halves2bfloat162(
        __float2bfloat16(v.x - __bfloat162float(h0)),
        __float2bfloat16(v.y - __bfloat162float(h1)));
    *(__nv_bfloat162*)(lo + o + 2) = __halves2bfloat162(
        __float2bfloat16(v.z - __bfloat162float(h2)),
        __float2bfloat16(v.w - __bfloat162float(h3)));
}

// =====================================================================
// RoPE + scale + bf16 split; input row stride 4096 with column offset
// =====================================================================
__global__ void rope_split_kernel(const float* __restrict__ buf, int coloff,
                                  const float* __restrict__ cosb,
                                  const float* __restrict__ sinb,
                                  __nv_bfloat16* __restrict__ oh,
                                  __nv_bfloat16* __restrict__ ol,
                                  int nheads, float scale)
{
    int idx = blockIdx.x * blockDim.x + threadIdx.x;
    int total = 4096 * nheads * 128;
    if (idx >= total) return;
    int j = idx & 127;
    int h = (idx >> 7) % nheads;
    int n = idx / (128 * nheads);
    int t = n & (S_LEN - 1);
    size_t ibase = (size_t)n * 4096 + coloff + h * 256 + j;
    size_t obase = (size_t)n * (nheads * 256) + h * 256 + j;
    float x1 = buf[ibase];
    float x2 = buf[ibase + 128];
    float c = cosb[t * 128 + j];
    float s = sinb[t * 128 + j];
    float y1 = (x1 * c - x2 * s) * scale;
    float y2 = (x1 * s + x2 * c) * scale;
    __nv_bfloat16 h1 = __float2bfloat16(y1);
    __nv_bfloat16 h2v = __float2bfloat16(y2);
    oh[obase]       = h1;
    oh[obase + 128] = h2v;
    ol[obase]       = __float2bfloat16(y1 - __bfloat162float(h1));
    ol[obase + 128] = __float2bfloat16(y2 - __bfloat162float(h2v));
}

// =====================================================================
// HMMA GEMM: 128x128 tile, K-chunk 32, 2-stage, 2 CTAs/SM.
// B operand loaded via merged ldsm_x4 (mats {0,2}/{1,3} per n-row pair).
// =====================================================================
#define STAGES 2
#define TILE_B 10240
#define STAGE_B (4 * TILE_B)
#define GEMM_SMEM (STAGES * STAGE_B)   // 81920

__device__ __forceinline__ void issue_stage(
    uint32_t sb, int c, int tid, int m0, int n0, int K,
    const __nv_bfloat16* Ah, const __nv_bfloat16* Al,
    const __nv_bfloat16* Bh, const __nv_bfloat16* Bl)
{
    uint32_t st = sb + (uint32_t)(c & 1) * STAGE_B;
    int k0 = c * 32;
#pragma unroll
    for (int half = 0; half < 2; half++) {
        int idx = tid + half * 256;
        int row = idx >> 2;
        int seg = idx & 3;
        uint32_t so = (uint32_t)(row * 80 + seg * 16);
        size_t ga = (size_t)(m0 + row) * K + k0 + seg * 8;
        size_t gb = (size_t)(n0 + row) * K + k0 + seg * 8;
        cp_async16(st + so,              Ah + ga);
        cp_async16(st + TILE_B + so,     Al + ga);
        cp_async16(st + 2 * TILE_B + so, Bh + gb);
        cp_async16(st + 3 * TILE_B + so, Bl + gb);
    }
    CP_COMMIT();
}

__global__ __launch_bounds__(256, 2) void gemm_hmma(
    const __nv_bfloat16* __restrict__ Ah, const __nv_bfloat16* __restrict__ Al,
    const __nv_bfloat16* __restrict__ Bh, const __nv_bfloat16* __restrict__ Bl,
    float* __restrict__ C, int M, int N, int K)
{
    extern __shared__ __align__(128) char smem[];
    const uint32_t sb = smem_u32(smem);
    const int tid = threadIdx.x;
    const int wid = tid >> 5, lane = tid & 31;
    const int wm = wid >> 2, wn = wid & 3;
    const int m0 = blockIdx.y * 128, n0 = blockIdx.x * 128;

    float acc[4][4][4];
#pragma unroll
    for (int mi = 0; mi < 4; mi++)
#pragma unroll
        for (int ni = 0; ni < 4; ni++)
#pragma unroll
            for (int r = 0; r < 4; r++) acc[mi][ni][r] = 0.f;

    const int NC = K >> 5;
    issue_stage(sb, 0, tid, m0, n0, K, Ah, Al, Bh, Bl);

    const uint32_t aoff = (uint32_t)((wm * 64 + (lane & 15)) * 80 +
                                     (lane >> 4) * 16);
    // merged B addressing: 16-row x4 footprint (same pattern as A)
    const uint32_t boff = (uint32_t)((wn * 32 + (lane & 15)) * 80 +
                                     (lane >> 4) * 16);

    for (int c = 0; c < NC; c++) {
        if (c + 1 < NC)
            issue_stage(sb, c + 1, tid, m0, n0, K, Ah, Al, Bh, Bl);
        if (c + 1 < NC) CP_WAIT1(); else CP_WAIT0();
        __syncthreads();
        const uint32_t st = sb + (uint32_t)(c & 1) * STAGE_B;
        const uint32_t aA = st + aoff;
        const uint32_t aB = st + 2 * TILE_B + boff;

#pragma unroll
        for (int ks = 0; ks < 2; ks++) {
            uint32_t ah[4][4], al[4][4], bh4[2][4], bl4[2][4];
#pragma unroll
            for (int mi = 0; mi < 4; mi++)
                ldsm_x4(ah[mi], aA + mi * (16 * 80) + ks * 32);
#pragma unroll
            for (int p = 0; p < 2; p++) {
                ldsm_x4(bh4[p], aB + p * (16 * 80) + ks * 32);
                ldsm_x4(bl4[p], aB + TILE_B + p * (16 * 80) + ks * 32);
            }
            // bh[ni] = { bh4[ni>>1][ni&1], bh4[ni>>1][(ni&1)+2] }
#pragma unroll
            for (int mi = 0; mi < 4; mi++)
#pragma unroll
                for (int ni = 0; ni < 4; ni++) {
                    mma16816s(acc[mi][ni], ah[mi],
                              bh4[ni >> 1][ni & 1], bh4[ni >> 1][(ni & 1) + 2]);
                    mma16816s(acc[mi][ni], ah[mi],
                              bl4[ni >> 1][ni & 1], bl4[ni >> 1][(ni & 1) + 2]);
                }
#pragma unroll
            for (int mi = 0; mi < 4; mi++)
                ldsm_x4(al[mi], aA + TILE_B + mi * (16 * 80) + ks * 32);
#pragma unroll
            for (int mi = 0; mi < 4; mi++)
#pragma unroll
                for (int ni = 0; ni < 4; ni++)
                    mma16816s(acc[mi][ni], al[mi],
                              bh4[ni >> 1][ni & 1], bh4[ni >> 1][(ni & 1) + 2]);
        }
        __syncthreads();
    }

    const int gr = lane >> 2, cn = lane & 3;
#pragma unroll
    for (int mi = 0; mi < 4; mi++) {
        int r = m0 + wm * 64 + mi * 16 + gr;
#pragma unroll
        for (int ni = 0; ni < 4; ni++) {
            int col = n0 + wn * 32 + ni * 8 + cn * 2;
            *(float2*)(C + (size_t)r * N + col) =
                make_float2(acc[mi][ni][0], acc[mi][ni][1]);
            *(float2*)(C + (size_t)(r + 8) * N + col) =
                make_float2(acc[mi][ni][2], acc[mi][ni][3]);
        }
    }
}

// =====================================================================
// HMMA attention with K-tile prefetch (R11) + merged B ldsm_x4 in S loop.
// =====================================================================
#define DP 528
#define PP 144
#define SM_QH 0
#define SM_QL (64 * DP)
#define SM_KH (2 * 64 * DP)
#define SM_KL (3 * 64 * DP)
#define SM_VH (4 * 64 * DP)
#define SM_VL (5 * 64 * DP)
#define SM_PH (6 * 64 * DP)
#define SM_PL (SM_PH + 64 * PP)
#define SM_LS (SM_PL + 64 * PP)
#define ATT_SMEM (SM_LS + 256)

__device__ __forceinline__ float capexp(float s, int ig, int jg) {
    float x = s * INV_CAP;
    x = fminf(fmaxf(x, -15.f), 15.f);
    float e = __expf(2.f * x);
    bool win = (jg <= ig) && (ig - jg < 1024);
    // p = exp(50*tanh(x) - 50) = exp(-100/(e+1))
    return win ? __expf(__fdividef(-100.f, e + 1.f)) : 0.f;
}

__global__ __launch_bounds__(256, 1) void attn_hmma(
    const __nv_bfloat16* __restrict__ qh, const __nv_bfloat16* __restrict__ ql,
    const __nv_bfloat16* __restrict__ kh, const __nv_bfloat16* __restrict__ kl,
    const __nv_bfloat16* __restrict__ vh, const __nv_bfloat16* __restrict__ vl,
    float* __restrict__ probs, float* __restrict__ attn_out,
    __nv_bfloat16* __restrict__ gath, __nv_bfloat16* __restrict__ gatl,
    float* __restrict__ linv)
{
    extern __shared__ __align__(128) char smem[];
    const uint32_t sb = smem_u32(smem);
    float* smls = (float*)(smem + SM_LS);
    const int tid = threadIdx.x, wid = tid >> 5, lane = tid & 31;
    const int wm = wid >> 1, wn = wid & 1;
    const int gr = lane >> 2, cn = lane & 3;
    const int q0 = (gridDim.x - 1 - blockIdx.x) * 64;
    const int h = blockIdx.y, b = blockIdx.z;
    const int hkv = h >> 1, bh = b * NH + h;

    const int kstart = max(0, q0 - 1024);

    // prologue: Q tile + first K tile in one cp.async group
#pragma unroll
    for (int i = 0; i < 8; i++) {
        int seg = tid + i * 256;
        int r = seg >> 5, s = seg & 31;
        size_t g = ((size_t)(b * S_LEN + q0 + r)) * 2048 + h * 256 + s * 8;
        cp_async16(sb + SM_QH + r * DP + s * 16, qh + g);
        cp_async16(sb + SM_QL + r * DP + s * 16, ql + g);
    }
#pragma unroll
    for (int i = 0; i < 8; i++) {
        int seg = tid + i * 256;
        int r = seg >> 5, s = seg & 31;
        size_t g = ((size_t)(b * S_LEN + kstart + r)) * 1024 + hkv * 256 + s * 8;
        cp_async16(sb + SM_KH + r * DP + s * 16, kh + g);
        cp_async16(sb + SM_KL + r * DP + s * 16, kl + g);
    }
    CP_COMMIT();
    if (tid < 64) smls[tid] = 0.f;

    float acco[16][4];
#pragma unroll
    for (int i = 0; i < 16; i++)
#pragma unroll
        for (int r = 0; r < 4; r++) acco[i][r] = 0.f;

    const int qg0 = q0 + wm * 16 + gr;
    const int qg1 = qg0 + 8;

    for (int kt0 = kstart; kt0 <= q0; kt0 += 64) {
        CP_WAIT0();
        __syncthreads();

        // issue V_kt (hides behind S compute)
#pragma unroll
        for (int i = 0; i < 8; i++) {
            int seg = tid + i * 256;
            int r = seg >> 5, s = seg & 31;
            size_t g = ((size_t)(b * S_LEN + kt0 + r)) * 1024 + hkv * 256 + s * 8;
            cp_async16(sb + SM_VH + r * DP + s * 16, vh + g);
            cp_async16(sb + SM_VL + r * DP + s * 16, vl + g);
        }
        CP_COMMIT();

        // ---- S = Q K^T (merged B x4 loads) ----
        float sacc[4][4];
#pragma unroll
        for (int ni = 0; ni < 4; ni++)
#pragma unroll
            for (int r = 0; r < 4; r++) sacc[ni][r] = 0.f;

        const uint32_t qa = sb + SM_QH + (wm * 16 + (lane & 15)) * DP +
                            (lane >> 4) * 16;
        const uint32_t kb = sb + SM_KH + (wn * 32 + (lane & 15)) * DP +
                            (lane >> 4) * 16;
#pragma unroll 4
        for (int kc = 0; kc < 16; kc++) {
            uint32_t ah[4], al[4], bh4[2][4], bl4[2][4];
            ldsm_x4(ah, qa + kc * 32);
            ldsm_x4(al, qa + (SM_QL - SM_QH) + kc * 32);
#pragma unroll
            for (int p = 0; p < 2; p++) {
                ldsm_x4(bh4[p], kb + p * (16 * DP) + kc * 32);
                ldsm_x4(bl4[p], kb + (SM_KL - SM_KH) + p * (16 * DP) + kc * 32);
            }
#pragma unroll
            for (int ni = 0; ni < 4; ni++) {
                uint32_t b0h = bh4[ni >> 1][ni & 1];
                uint32_t b1h = bh4[ni >> 1][(ni & 1) + 2];
                uint32_t b0l = bl4[ni >> 1][ni & 1];
                uint32_t b1l = bl4[ni >> 1][(ni & 1) + 2];
                mma16816s(sacc[ni], ah, b0h, b1h);
                mma16816s(sacc[ni], ah, b0l, b1l);
                mma16816s(sacc[ni], al, b0h, b1h);
            }
        }

        // ---- softcap/exp, P split into smem, row sums ----
        float l0 = 0.f, l1 = 0.f;
#pragma unroll
        for (int ni = 0; ni < 4; ni++) {
            int keyb = kt0 + wn * 32 + ni * 8 + cn * 2;
            float p0 = capexp(sacc[ni][0], qg0, keyb);
            float p1 = capexp(sacc[ni][1], qg0, keyb + 1);
            float p2 = capexp(sacc[ni][2], qg1, keyb);
            float p3 = capexp(sacc[ni][3], qg1, keyb + 1);
            l0 += p0 + p1;
            l1 += p2 + p3;
            __nv_bfloat16 h0 = __float2bfloat16(p0), h1 = __float2bfloat16(p1);
            __nv_bfloat16 h2 = __float2bfloat16(p2), h3 = __float2bfloat16(p3);
            int pcol = (wn * 32 + ni * 8 + cn * 2) * 2;
            int pr0 = (wm * 16 + gr) * PP, pr1 = pr0 + 8 * PP;
            *(__nv_bfloat162*)(smem + SM_PH + pr0 + pcol) = __halves2bfloat162(h0, h1);
            *(__nv_bfloat162*)(smem + SM_PH + pr1 + pcol) = __halves2bfloat162(h2, h3);
            *(__nv_bfloat162*)(smem + SM_PL + pr0 + pcol) = __halves2bfloat162(
                __float2bfloat16(p0 - __bfloat162float(h0)),
                __float2bfloat16(p1 - __bfloat162float(h1)));
            *(__nv_bfloat162*)(smem + SM_PL + pr1 + pcol) = __halves2bfloat162(
                __float2bfloat16(p2 - __bfloat162float(h2)),
                __float2bfloat16(p3 - __bfloat162float(h3)));
        }
        l0 += __shfl_xor_sync(0xffffffffu, l0, 1);
        l0 += __shfl_xor_sync(0xffffffffu, l0, 2);
        l1 += __shfl_xor_sync(0xffffffffu, l1, 1);
        l1 += __shfl_xor_sync(0xffffffffu, l1, 2);
        if (cn == 0) {
            atomicAdd(&smls[wm * 16 + gr], l0);
            atomicAdd(&smls[wm * 16 + gr + 8], l1);
        }

        CP_WAIT0();          // V ready (K_next not yet committed)
        __syncthreads();     // P visible; K-buffer reads done

        // prefetch NEXT K tile (hides behind probs writeback + PV)
        if (kt0 + 64 <= q0) {
#pragma unroll
            for (int i = 0; i < 8; i++) {
                int seg = tid + i * 256;
                int r = seg >> 5, s = seg & 31;
                size_t g = ((size_t)(b * S_LEN + kt0 + 64 + r)) * 1024 +
                           hkv * 256 + s * 8;
                cp_async16(sb + SM_KH + r * DP + s * 16, kh + g);
                cp_async16(sb + SM_KL + r * DP + s * 16, kl + g);
            }
            CP_COMMIT();
        }

        // ---- coalesced probs writeback from smem P (hi+lo) ----
#pragma unroll
        for (int i = 0; i < 4; i++) {
            int idx = tid + i * 256;
            int r = idx >> 4;
            int c4 = (idx & 15) * 4;
            uint2 vh2 = *(const uint2*)(smem + SM_PH + r * PP + c4 * 2);
            uint2 vl2 = *(const uint2*)(smem + SM_PL + r * PP + c4 * 2);
            float2 a0 = __bfloat1622float2(*(__nv_bfloat162*)&vh2.x);
            float2 a1 = __bfloat1622float2(*(__nv_bfloat162*)&vh2.y);
            float2 b0 = __bfloat1622float2(*(__nv_bfloat162*)&vl2.x);
            float2 b1 = __bfloat1622float2(*(__nv_bfloat162*)&vl2.y);
            float4 pv;
            pv.x = a0.x + b0.x; pv.y = a0.y + b0.y;
            pv.z = a1.x + b1.x; pv.w = a1.y + b1.y;
            *(float4*)(probs + ((size_t)bh * S_LEN + q0 + r) * S_LEN + kt0 + c4) = pv;
        }

        // ---- O += P~ V ----
        const uint32_t pa = sb + SM_PH + (wm * 16 + (lane & 15)) * PP +
                            (lane >> 4) * 16;
        const uint32_t vb = sb + SM_VH + (lane & 15) * DP +
                            (wn * 128) * 2 + (lane >> 4) * 16;
#pragma unroll
        for (int kk = 0; kk < 4; kk++) {
            uint32_t ph[4], pl[4];
            ldsm_x4(ph, pa + kk * 32);
            ldsm_x4(pl, pa + (SM_PL - SM_PH) + kk * 32);
#pragma unroll
            for (int nj = 0; nj < 8; nj++) {
                uint32_t vbh[4], vbl[4];
                uint32_t va = vb + kk * (16 * DP) + nj * 32;
                ldsm_x4t(vbh, va);
                ldsm_x4t(vbl, va + (SM_VL - SM_VH));
                mma16816(acco[nj * 2], ph, vbh);
                mma16816(acco[nj * 2], ph, vbl);
                mma16816(acco[nj * 2], pl, vbh);
                mma16816(acco[nj * 2 + 1], ph, vbh + 2);
                mma16816(acco[nj * 2 + 1], ph, vbl + 2);
                mma16816(acco[nj * 2 + 1], pl, vbh + 2);
            }
        }
        // trailing sync elided: next iteration's CP_WAIT0 + __syncthreads
    }
    __syncthreads();

    // ---- final epilogue ----
    if (tid < 64)
        linv[(size_t)bh * S_LEN + q0 + tid] = 1.f / smls[tid];
    float inv0 = 1.f / smls[wm * 16 + gr];
    float inv1 = 1.f / smls[wm * 16 + gr + 8];
#pragma unroll
    for (int ni = 0; ni < 16; ni++) {
        int col = wn * 128 + ni * 8 + cn * 2;
        float o0 = acco[ni][0] * inv0, o1 = acco[ni][1] * inv0;
        float o2 = acco[ni][2] * inv1, o3 = acco[ni][3] * inv1;
        *(float2*)(attn_out + ((size_t)bh * S_LEN + qg0) * 256 + col) =
            make_float2(o0, o1);
        *(float2*)(attn_out + ((size_t)bh * S_LEN + qg1) * 256 + col) =
            make_float2(o2, o3);
        size_t ga0 = ((size_t)(b * S_LEN) + qg0) * 2048 + h * 256 + col;
        size_t ga1 = ((size_t)(b * S_LEN) + qg1) * 2048 + h * 256 + col;
        __nv_bfloat16 h0 = __float2bfloat16(o0), h1 = __float2bfloat16(o1);
        __nv_bfloat16 h2 = __float2bfloat16(o2), h3 = __float2bfloat16(o3);
        *(__nv_bfloat162*)(gath + ga0) = __halves2bfloat162(h0, h1);
        *(__nv_bfloat162*)(gath + ga1) = __halves2bfloat162(h2, h3);
        *(__nv_bfloat162*)(gatl + ga0) = __halves2bfloat162(
            __float2bfloat16(o0 - __bfloat162float(h0)),
            __float2bfloat16(o1 - __bfloat162float(h1)));
        *(__nv_bfloat162*)(gatl + ga1) = __halves2bfloat162(
            __float2bfloat16(o2 - __bfloat162float(h2)),
            __float2bfloat16(o3 - __bfloat162float(h3)));
    }
}

// =====================================================================
// Full-row probs finalize: zero outside the band, scale inside.
// =====================================================================
__global__ void norm_probs_full(float* __restrict__ probs,
                                const float* __restrict__ linv)
{
    int row = blockIdx.x;
    int i = row & (S_LEN - 1);
    float inv = linv[row];
    int lo = max(0, i - 1023);
    float4* p = (float4*)(probs + (size_t)row * S_LEN);
#pragma unroll
    for (int c = (int)threadIdx.x; c < 512; c += 256) {
        int c0 = c << 2;
        float4 v;
        if (c0 + 3 < lo || c0 > i) {
            v = make_float4(0.f, 0.f, 0.f, 0.f);
        } else {
            v = p[c];
            v.x = (c0 >= lo && c0 <= i)         ? v.x * inv : 0.f;
            v.y = (c0 + 1 >= lo && c0 + 1 <= i) ? v.y * inv : 0.f;
            v.z = (c0 + 2 >= lo && c0 + 2 <= i) ? v.z * inv : 0.f;
            v.w = (c0 + 3 >= lo && c0 + 3 <= i) ? v.w * inv : 0.f;
        }
        p[c] = v;
    }
}

// =====================================================================
// Outputs: out[2,2048,2048] @0 | probs @8388608 | attn @75497472
// Stream fork/join (capture-legal, validated R10/R11).
// =====================================================================
extern "C" void kernel_launch(void* const* d_in, const int* in_sizes, int n_in,
                              void* d_out, int out_size)
{
    const float* hs = (const float*)d_in[0];
    const float* fc = (const float*)d_in[1];
    const float* fs = (const float*)d_in[2];
    const float* wq = (const float*)d_in[4];
    const float* wk = (const float*)d_in[5];
    const float* wv = (const float*)d_in[6];
    const float* wo = (const float*)d_in[7];

    float* out   = (float*)d_out;
    float* probs = out + 8388608ull;
    float* attn  = probs + 67108864ull;

    float *gqkv, *glinv;
    cudaGetSymbolAddress((void**)&gqkv, g_qkv);
    cudaGetSymbolAddress((void**)&glinv, g_linv);

    void *hsh, *hsl, *atth, *attl, *wh, *wl, *woh, *wol;
    void *qh, *ql, *kh, *kl, *vh, *vl;
    cudaGetSymbolAddress(&hsh, g_hs_h);  cudaGetSymbolAddress(&hsl, g_hs_l);
    cudaGetSymbolAddress(&atth, g_att_h); cudaGetSymbolAddress(&attl, g_att_l);
    cudaGetSymbolAddress(&wh, g_w_h);    cudaGetSymbolAddress(&wl, g_w_l);
    cudaGetSymbolAddress(&woh, g_wo_h);  cudaGetSymbolAddress(&wol, g_wo_l);
    cudaGetSymbolAddress(&qh, g_qh);     cudaGetSymbolAddress(&ql, g_ql);
    cudaGetSymbolAddress(&kh, g_kh);     cudaGetSymbolAddress(&kl, g_kl);
    cudaGetSymbolAddress(&vh, g_vh);     cudaGetSymbolAddress(&vl, g_vl);

    cudaFuncSetAttribute(gemm_hmma,
                         cudaFuncAttributeMaxDynamicSharedMemorySize, GEMM_SMEM);
    cudaFuncSetAttribute(attn_hmma,
                         cudaFuncAttributeMaxDynamicSharedMemorySize, ATT_SMEM);

    static cudaStream_t s1 = nullptr;
    static cudaEvent_t eStart, eW, eWo, eGemm, eP, eAtt, eNorm;
    if (!s1) {
        cudaStreamCreateWithFlags(&s1, cudaStreamNonBlocking);
        cudaEventCreateWithFlags(&eStart, cudaEventDisableTiming);
        cudaEventCreateWithFlags(&eW,     cudaEventDisableTiming);
        cudaEventCreateWithFlags(&eWo,    cudaEventDisableTiming);
        cudaEventCreateWithFlags(&eGemm,  cudaEventDisableTiming);
        cudaEventCreateWithFlags(&eP,     cudaEventDisableTiming);
        cudaEventCreateWithFlags(&eAtt,   cudaEventDisableTiming);
        cudaEventCreateWithFlags(&eNorm,  cudaEventDisableTiming);
    }

    __nv_bfloat16* whb = (__nv_bfloat16*)wh;
    __nv_bfloat16* wlb = (__nv_bfloat16*)wl;

    // fork: side stream handles weight splits while main does hs split
    cudaEventRecord(eStart, 0);
    cudaStreamWaitEvent(s1, eStart, 0);

    split_kernel<<<8192, 256>>>(hs, (__nv_bfloat16*)hsh, (__nv_bfloat16*)hsl,
                                2097152);

    split_kernel<<<4096, 256, 0, s1>>>(wq, whb, wlb, 1048576);
    split_kernel<<<2048, 256, 0, s1>>>(wk, whb + 2048ull * 2048,
                                       wlb + 2048ull * 2048, 524288);
    split_kernel<<<2048, 256, 0, s1>>>(wv, whb + 3072ull * 2048,
                                       wlb + 3072ull * 2048, 524288);
    cudaEventRecord(eW, s1);
    split_kernel<<<4096, 256, 0, s1>>>(wo, (__nv_bfloat16*)woh,
                                       (__nv_bfloat16*)wol, 1048576);
    cudaEventRecord(eWo, s1);

    // main: QKV GEMM
    cudaStreamWaitEvent(0, eW, 0);
    gemm_hmma<<<dim3(32, 32), 256, GEMM_SMEM>>>(
        (const __nv_bfloat16*)hsh, (const __nv_bfloat16*)hsl,
        whb, wlb, gqkv, 4096, 4096, 2048);
    cudaEventRecord(eGemm, 0);

    // fork: rope_k + v split on s1, rope_q on main
    cudaStreamWaitEvent(s1, eGemm, 0);
    rope_split_kernel<<<8192, 256, 0, s1>>>(gqkv, 2048, fc, fs,
                                            (__nv_bfloat16*)kh,
                                            (__nv_bfloat16*)kl, 4, 1.0f);
    split_strided_kernel<<<4096, 256, 0, s1>>>(gqkv, 3072, (__nv_bfloat16*)vh,
                                               (__nv_bfloat16*)vl);
    cudaEventRecord(eP, s1);

    rope_split_kernel<<<16384, 256>>>(gqkv, 0, fc, fs, (__nv_bfloat16*)qh,
                                      (__nv_bfloat16*)ql, 8, QSCALE);
    cudaStreamWaitEvent(0, eP, 0);

    // attention on main
    attn_hmma<<<dim3(32, 8, 2), 256, ATT_SMEM>>>(
        (const __nv_bfloat16*)qh, (const __nv_bfloat16*)ql,
        (const __nv_bfloat16*)kh, (const __nv_bfloat16*)kl,
        (const __nv_bfloat16*)vh, (const __nv_bfloat16*)vl,
        probs, attn, (__nv_bfloat16*)atth, (__nv_bfloat16*)attl, glinv);
    cudaEventRecord(eAtt, 0);

    // fork: probs normalize on s1, concurrent with wo GEMM on main
    cudaStreamWaitEvent(s1, eAtt, 0);
    norm_probs_full<<<32768, 256, 0, s1>>>(probs, glinv);
    cudaEventRecord(eNorm, s1);

    cudaStreamWaitEvent(0, eWo, 0);
    gemm_hmma<<<dim3(16, 32), 256, GEMM_SMEM>>>(
        (const __nv_bfloat16*)atth, (const __nv_bfloat16*)attl,
        (const __nv_bfloat16*)woh, (const __nv_bfloat16*)wol, out,
        4096, 2048, 2048);

    // join side stream back into main before returning
    cudaStreamWaitEvent(0, eNorm, 0);
}

// round 13
// speedup vs baseline: 1.1479x; 1.1479x over previous
#include <cuda_runtime.h>
#include <cuda_bf16.h>
#include <math.h>
#include <stdint.h>

#define S_LEN 2048
#define HID   2048
#define NH    8
#define NKV   4
#define HD    256
#define QSCALE 0.0625f       // D^-0.5
#define INV_CAP 0.02f        // 1/50
#define CAP    50.0f

// ---- fp32 scratch ----
__device__ float g_qkv[(size_t)4096 * 4096];   // q cols 0-2047 | k 2048-3071 | v 3072-4095
__device__ float g_linv[32768];

// ---- bf16 split scratch ----
__device__ uint4 g_hs_h[(size_t)4096 * 2048 / 8];
__device__ uint4 g_hs_l[(size_t)4096 * 2048 / 8];
__device__ uint4 g_att_h[(size_t)4096 * 2048 / 8];
__device__ uint4 g_att_l[(size_t)4096 * 2048 / 8];
__device__ uint4 g_w_h[(size_t)4096 * 2048 / 8];   // wq rows 0-2047 | wk | wv
__device__ uint4 g_w_l[(size_t)4096 * 2048 / 8];
__device__ uint4 g_wo_h[(size_t)2048 * 2048 / 8];
__device__ uint4 g_wo_l[(size_t)2048 * 2048 / 8];
__device__ uint4 g_qh[(size_t)4096 * 2048 / 8];
__device__ uint4 g_ql[(size_t)4096 * 2048 / 8];
__device__ uint4 g_kh[(size_t)4096 * 1024 / 8];
__device__ uint4 g_kl[(size_t)4096 * 1024 / 8];
__device__ uint4 g_vh[(size_t)4096 * 1024 / 8];
__device__ uint4 g_vl[(size_t)4096 * 1024 / 8];

// =====================================================================
// helpers
// =====================================================================
__device__ __forceinline__ uint32_t smem_u32(const void* p) {
    uint32_t a;
    asm("{ .reg .u64 t; cvta.to.shared.u64 t, %1; cvt.u32.u64 %0, t; }"
        : "=r"(a) : "l"(p));
    return a;
}
__device__ __forceinline__ void cp_async16(uint32_t saddr, const void* gaddr) {
    asm volatile("cp.async.cg.shared.global [%0], [%1], 16;"
                 :: "r"(saddr), "l"(gaddr) : "memory");
}
#define CP_COMMIT() asm volatile("cp.async.commit_group;" ::: "memory")
#define CP_WAIT1()  asm volatile("cp.async.wait_group 1;" ::: "memory")
#define CP_WAIT0()  asm volatile("cp.async.wait_group 0;" ::: "memory")

__device__ __forceinline__ void ldsm_x4(uint32_t* r, uint32_t addr) {
    asm volatile("ldmatrix.sync.aligned.m8n8.x4.shared.b16 {%0,%1,%2,%3}, [%4];"
                 : "=r"(r[0]), "=r"(r[1]), "=r"(r[2]), "=r"(r[3]) : "r"(addr));
}
__device__ __forceinline__ void ldsm_x4t(uint32_t* r, uint32_t addr) {
    asm volatile("ldmatrix.sync.aligned.m8n8.x4.trans.shared.b16 {%0,%1,%2,%3}, [%4];"
                 : "=r"(r[0]), "=r"(r[1]), "=r"(r[2]), "=r"(r[3]) : "r"(addr));
}
__device__ __forceinline__ void ldsm_x2(uint32_t* r, uint32_t addr) {
    asm volatile("ldmatrix.sync.aligned.m8n8.x2.shared.b16 {%0,%1}, [%2];"
                 : "=r"(r[0]), "=r"(r[1]) : "r"(addr));
}
__device__ __forceinline__ void mma16816(float* c, const uint32_t* a,
                                         const uint32_t* b) {
    asm volatile(
        "mma.sync.aligned.m16n8k16.row.col.f32.bf16.bf16.f32 "
        "{%0,%1,%2,%3}, {%4,%5,%6,%7}, {%8,%9}, {%0,%1,%2,%3};"
        : "+f"(c[0]), "+f"(c[1]), "+f"(c[2]), "+f"(c[3])
        : "r"(a[0]), "r"(a[1]), "r"(a[2]), "r"(a[3]), "r"(b[0]), "r"(b[1]));
}

// =====================================================================
// split fp32 -> (hi, lo) bf16  (contiguous)
// =====================================================================
__global__ void split_kernel(const float* __restrict__ x,
                             __nv_bfloat16* __restrict__ hi,
                             __nv_bfloat16* __restrict__ lo, int n4)
{
    int i = blockIdx.x * blockDim.x + threadIdx.x;
    if (i >= n4) return;
    float4 v = ((const float4*)x)[i];
    __nv_bfloat16 h0 = __float2bfloat16(v.x);
    __nv_bfloat16 h1 = __float2bfloat16(v.y);
    __nv_bfloat16 h2 = __float2bfloat16(v.z);
    __nv_bfloat16 h3 = __float2bfloat16(v.w);
    __nv_bfloat16 l0 = __float2bfloat16(v.x - __bfloat162float(h0));
    __nv_bfloat16 l1 = __float2bfloat16(v.y - __bfloat162float(h1));
    __nv_bfloat16 l2 = __float2bfloat16(v.z - __bfloat162float(h2));
    __nv_bfloat16 l3 = __float2bfloat16(v.w - __bfloat162float(h3));
    __nv_bfloat162* h2p = (__nv_bfloat162*)hi;
    __nv_bfloat162* l2p = (__nv_bfloat162*)lo;
    h2p[2 * i]     = __halves2bfloat162(h0, h1);
    h2p[2 * i + 1] = __halves2bfloat162(h2, h3);
    l2p[2 * i]     = __halves2bfloat162(l0, l1);
    l2p[2 * i + 1] = __halves2bfloat162(l2, l3);
}

// =====================================================================
// split fp32 submatrix (row stride 4096, col offset) -> bf16 hi/lo [., 1024]
// =====================================================================
__global__ void split_strided_kernel(const float* __restrict__ x, int coloff,
                                     __nv_bfloat16* __restrict__ hi,
                                     __nv_bfloat16* __restrict__ lo)
{
    int i = blockIdx.x * blockDim.x + threadIdx.x;
    if (i >= 4096 * 256) return;
    int row = i >> 8, c4 = (i & 255) << 2;
    float4 v = *(const float4*)(x + (size_t)row * 4096 + coloff + c4);
    __nv_bfloat16 h0 = __float2bfloat16(v.x);
    __nv_bfloat16 h1 = __float2bfloat16(v.y);
    __nv_bfloat16 h2 = __float2bfloat16(v.z);
    __nv_bfloat16 h3 = __float2bfloat16(v.w);
    size_t o = (size_t)row * 1024 + c4;
    *(__nv_bfloat162*)(hi + o)     = __halves2bfloat162(h0, h1);
    *(__nv_bfloat162*)(hi + o + 2) = __halves2bfloat162(h2, h3);
    *(__nv_bfloat162*)(lo + o)     = __halves2bfloat162(
        __float2bfloat16(v.x - __bfloat162float(h0)),
        __float2bfloat16(v.y - __bfloat162float(h1)));
    *(__nv_bfloat162*)(lo + o + 2) = __halves2bfloat162(
        __float2bfloat16(v.z - __bfloat162float(h2)),
        __float2bfloat16(v.w - __bfloat162float(h3)));
}

// =====================================================================
// RoPE + scale + bf16 split; input row stride 4096 with column offset
// =====================================================================
__global__ void rope_split_kernel(const float* __restrict__ buf, int coloff,
                                  const float* __restrict__ cosb,
                                  const float* __restrict__ sinb,
                                  __nv_bfloat16* __restrict__ oh,
                                  __nv_bfloat16* __restrict__ ol,
                                  int nheads, float scale)
{
    int idx = blockIdx.x * blockDim.x + threadIdx.x;
    int total = 4096 * nheads * 128;
    if (idx >= total) return;
    int j = idx & 127;
    int h = (idx >> 7) % nheads;
    int n = idx / (128 * nheads);
    int t = n & (S_LEN - 1);
    size_t ibase = (size_t)n * 4096 + coloff + h * 256 + j;
    size_t obase = (size_t)n * (nheads * 256) + h * 256 + j;
    float x1 = buf[ibase];
    float x2 = buf[ibase + 128];
    float c = cosb[t * 128 + j];
    float s = sinb[t * 128 + j];
    float y1 = (x1 * c - x2 * s) * scale;
    float y2 = (x1 * s + x2 * c) * scale;
    __nv_bfloat16 h1 = __float2bfloat16(y1);
    __nv_bfloat16 h2v = __float2bfloat16(y2);
    oh[obase]       = h1;
    oh[obase + 128] = h2v;
    ol[obase]       = __float2bfloat16(y1 - __bfloat162float(h1));
    ol[obase + 128] = __float2bfloat16(y2 - __bfloat162float(h2v));
}

// =====================================================================
// HMMA GEMM (R7/R11 config — validated best): 128x128 tile, K-chunk 32,
// 2-stage pipeline, 80KB smem, 2 CTAs/SM. B via ldsm_x2 (validated).
// =====================================================================
#define STAGES 2
#define TILE_B 10240
#define STAGE_B (4 * TILE_B)
#define GEMM_SMEM (STAGES * STAGE_B)   // 81920

__device__ __forceinline__ void issue_stage(
    uint32_t sb, int c, int tid, int m0, int n0, int K,
    const __nv_bfloat16* Ah, const __nv_bfloat16* Al,
    const __nv_bfloat16* Bh, const __nv_bfloat16* Bl)
{
    uint32_t st = sb + (uint32_t)(c & 1) * STAGE_B;
    int k0 = c * 32;
#pragma unroll
    for (int half = 0; half < 2; half++) {
        int idx = tid + half * 256;
        int row = idx >> 2;
        int seg = idx & 3;
        uint32_t so = (uint32_t)(row * 80 + seg * 16);
        size_t ga = (size_t)(m0 + row) * K + k0 + seg * 8;
        size_t gb = (size_t)(n0 + row) * K + k0 + seg * 8;
        cp_async16(st + so,              Ah + ga);
        cp_async16(st + TILE_B + so,     Al + ga);
        cp_async16(st + 2 * TILE_B + so, Bh + gb);
        cp_async16(st + 3 * TILE_B + so, Bl + gb);
    }
    CP_COMMIT();
}

__global__ __launch_bounds__(256, 2) void gemm_hmma(
    const __nv_bfloat16* __restrict__ Ah, const __nv_bfloat16* __restrict__ Al,
    const __nv_bfloat16* __restrict__ Bh, const __nv_bfloat16* __restrict__ Bl,
    float* __restrict__ C, int M, int N, int K)
{
    extern __shared__ __align__(128) char smem[];
    const uint32_t sb = smem_u32(smem);
    const int tid = threadIdx.x;
    const int wid = tid >> 5, lane = tid & 31;
    const int wm = wid >> 2, wn = wid & 3;
    const int m0 = blockIdx.y * 128, n0 = blockIdx.x * 128;

    float acc[4][4][4];
#pragma unroll
    for (int mi = 0; mi < 4; mi++)
#pragma unroll
        for (int ni = 0; ni < 4; ni++)
#pragma unroll
            for (int r = 0; r < 4; r++) acc[mi][ni][r] = 0.f;

    const int NC = K >> 5;
    issue_stage(sb, 0, tid, m0, n0, K, Ah, Al, Bh, Bl);

    const uint32_t aoff = (uint32_t)((wm * 64 + (lane & 15)) * 80 +
                                     (lane >> 4) * 16);
    const uint32_t boff = (uint32_t)((wn * 32 + (lane & 7)) * 80 +
                                     ((lane >> 3) & 1) * 16);

    for (int c = 0; c < NC; c++) {
        if (c + 1 < NC)
            issue_stage(sb, c + 1, tid, m0, n0, K, Ah, Al, Bh, Bl);
        if (c + 1 < NC) CP_WAIT1(); else CP_WAIT0();
        __syncthreads();
        const uint32_t st = sb + (uint32_t)(c & 1) * STAGE_B;
        const uint32_t aA = st + aoff;
        const uint32_t aB = st + 2 * TILE_B + boff;

#pragma unroll
        for (int ks = 0; ks < 2; ks++) {
            uint32_t ah[4][4], al[4][4], bh[4][2], bl[4][2];
#pragma unroll
            for (int mi = 0; mi < 4; mi++)
                ldsm_x4(ah[mi], aA + mi * (16 * 80) + ks * 32);
#pragma unroll
            for (int ni = 0; ni < 4; ni++) {
                ldsm_x2(bh[ni], aB + ni * (8 * 80) + ks * 32);
                ldsm_x2(bl[ni], aB + TILE_B + ni * (8 * 80) + ks * 32);
            }
#pragma unroll
            for (int mi = 0; mi < 4; mi++)
#pragma unroll
                for (int ni = 0; ni < 4; ni++) {
                    mma16816(acc[mi][ni], ah[mi], bh[ni]);
                    mma16816(acc[mi][ni], ah[mi], bl[ni]);
                }
#pragma unroll
            for (int mi = 0; mi < 4; mi++)
                ldsm_x4(al[mi], aA + TILE_B + mi * (16 * 80) + ks * 32);
#pragma unroll
            for (int mi = 0; mi < 4; mi++)
#pragma unroll
                for (int ni = 0; ni < 4; ni++)
                    mma16816(acc[mi][ni], al[mi], bh[ni]);
        }
        __syncthreads();
    }

    const int gr = lane >> 2, cn = lane & 3;
#pragma unroll
    for (int mi = 0; mi < 4; mi++) {
        int r = m0 + wm * 64 + mi * 16 + gr;
#pragma unroll
        for (int ni = 0; ni < 4; ni++) {
            int col = n0 + wn * 32 + ni * 8 + cn * 2;
            *(float2*)(C + (size_t)r * N + col) =
                make_float2(acc[mi][ni][0], acc[mi][ni][1]);
            *(float2*)(C + (size_t)(r + 8) * N + col) =
                make_float2(acc[mi][ni][2], acc[mi][ni][3]);
        }
    }
}

// =====================================================================
// HMMA attention with K-tile prefetch (R11, validated) + short capexp.
// =====================================================================
#define DP 528
#define PP 144
#define SM_QH 0
#define SM_QL (64 * DP)
#define SM_KH (2 * 64 * DP)
#define SM_KL (3 * 64 * DP)
#define SM_VH (4 * 64 * DP)
#define SM_VL (5 * 64 * DP)
#define SM_PH (6 * 64 * DP)
#define SM_PL (SM_PH + 64 * PP)
#define SM_LS (SM_PL + 64 * PP)
#define ATT_SMEM (SM_LS + 256)

__device__ __forceinline__ float capexp(float s, int ig, int jg) {
    float x = s * INV_CAP;
    x = fminf(fmaxf(x, -15.f), 15.f);
    float e = __expf(2.f * x);
    bool win = (jg <= ig) && (ig - jg < 1024);
    // p = exp(50*tanh(x) - 50) = exp(-100/(e+1))
    return win ? __expf(__fdividef(-100.f, e + 1.f)) : 0.f;
}

__global__ __launch_bounds__(256, 1) void attn_hmma(
    const __nv_bfloat16* __restrict__ qh, const __nv_bfloat16* __restrict__ ql,
    const __nv_bfloat16* __restrict__ kh, const __nv_bfloat16* __restrict__ kl,
    const __nv_bfloat16* __restrict__ vh, const __nv_bfloat16* __restrict__ vl,
    float* __restrict__ probs, float* __restrict__ attn_out,
    __nv_bfloat16* __restrict__ gath, __nv_bfloat16* __restrict__ gatl,
    float* __restrict__ linv)
{
    extern __shared__ __align__(128) char smem[];
    const uint32_t sb = smem_u32(smem);
    float* smls = (float*)(smem + SM_LS);
    const int tid = threadIdx.x, wid = tid >> 5, lane = tid & 31;
    const int wm = wid >> 1, wn = wid & 1;
    const int gr = lane >> 2, cn = lane & 3;
    const int q0 = (gridDim.x - 1 - blockIdx.x) * 64;
    const int h = blockIdx.y, b = blockIdx.z;
    const int hkv = h >> 1, bh = b * NH + h;

    const int kstart = max(0, q0 - 1024);

    // prologue: Q tile + first K tile in one cp.async group
#pragma unroll
    for (int i = 0; i < 8; i++) {
        int seg = tid + i * 256;
        int r = seg >> 5, s = seg & 31;
        size_t g = ((size_t)(b * S_LEN + q0 + r)) * 2048 + h * 256 + s * 8;
        cp_async16(sb + SM_QH + r * DP + s * 16, qh + g);
        cp_async16(sb + SM_QL + r * DP + s * 16, ql + g);
    }
#pragma unroll
    for (int i = 0; i < 8; i++) {
        int seg = tid + i * 256;
        int r = seg >> 5, s = seg & 31;
        size_t g = ((size_t)(b * S_LEN + kstart + r)) * 1024 + hkv * 256 + s * 8;
        cp_async16(sb + SM_KH + r * DP + s * 16, kh + g);
        cp_async16(sb + SM_KL + r * DP + s * 16, kl + g);
    }
    CP_COMMIT();
    if (tid < 64) smls[tid] = 0.f;

    float acco[16][4];
#pragma unroll
    for (int i = 0; i < 16; i++)
#pragma unroll
        for (int r = 0; r < 4; r++) acco[i][r] = 0.f;

    const int qg0 = q0 + wm * 16 + gr;
    const int qg1 = qg0 + 8;

    for (int kt0 = kstart; kt0 <= q0; kt0 += 64) {
        CP_WAIT0();          // K_kt ready (prologue or prefetched last iter)
        __syncthreads();     // also: all prior PV reads of V/P are done

        // issue V_kt (hides behind S compute)
#pragma unroll
        for (int i = 0; i < 8; i++) {
            int seg = tid + i * 256;
            int r = seg >> 5, s = seg & 31;
            size_t g = ((size_t)(b * S_LEN + kt0 + r)) * 1024 + hkv * 256 + s * 8;
            cp_async16(sb + SM_VH + r * DP + s * 16, vh + g);
            cp_async16(sb + SM_VL + r * DP + s * 16, vl + g);
        }
        CP_COMMIT();

        // ---- S = Q K^T ----
        float sacc[4][4];
#pragma unroll
        for (int ni = 0; ni < 4; ni++)
#pragma unroll
            for (int r = 0; r < 4; r++) sacc[ni][r] = 0.f;

        const uint32_t qa = sb + SM_QH + (wm * 16 + (lane & 15)) * DP +
                            (lane >> 4) * 16;
        const uint32_t kb = sb + SM_KH + (wn * 32 + (lane & 7)) * DP +
                            ((lane >> 3) & 1) * 16;
#pragma unroll 4
        for (int kc = 0; kc < 16; kc++) {
            uint32_t ah[4], al[4], bhf[4][2], blf[4][2];
            ldsm_x4(ah, qa + kc * 32);
            ldsm_x4(al, qa + (SM_QL - SM_QH) + kc * 32);
#pragma unroll
            for (int ni = 0; ni < 4; ni++) {
                ldsm_x2(bhf[ni], kb + ni * (8 * DP) + kc * 32);
                ldsm_x2(blf[ni], kb + (SM_KL - SM_KH) + ni * (8 * DP) + kc * 32);
            }
#pragma unroll
            for (int ni = 0; ni < 4; ni++) {
                mma16816(sacc[ni], ah, bhf[ni]);
                mma16816(sacc[ni], ah, blf[ni]);
                mma16816(sacc[ni], al, bhf[ni]);
            }
        }

        // ---- softcap/exp, P split into smem, row sums ----
        float l0 = 0.f, l1 = 0.f;
#pragma unroll
        for (int ni = 0; ni < 4; ni++) {
            int keyb = kt0 + wn * 32 + ni * 8 + cn * 2;
            float p0 = capexp(sacc[ni][0], qg0, keyb);
            float p1 = capexp(sacc[ni][1], qg0, keyb + 1);
            float p2 = capexp(sacc[ni][2], qg1, keyb);
            float p3 = capexp(sacc[ni][3], qg1, keyb + 1);
            l0 += p0 + p1;
            l1 += p2 + p3;
            __nv_bfloat16 h0 = __float2bfloat16(p0), h1 = __float2bfloat16(p1);
            __nv_bfloat16 h2 = __float2bfloat16(p2), h3 = __float2bfloat16(p3);
            int pcol = (wn * 32 + ni * 8 + cn * 2) * 2;
            int pr0 = (wm * 16 + gr) * PP, pr1 = pr0 + 8 * PP;
            *(__nv_bfloat162*)(smem + SM_PH + pr0 + pcol) = __halves2bfloat162(h0, h1);
            *(__nv_bfloat162*)(smem + SM_PH + pr1 + pcol) = __halves2bfloat162(h2, h3);
            *(__nv_bfloat162*)(smem + SM_PL + pr0 + pcol) = __halves2bfloat162(
                __float2bfloat16(p0 - __bfloat162float(h0)),
                __float2bfloat16(p1 - __bfloat162float(h1)));
            *(__nv_bfloat162*)(smem + SM_PL + pr1 + pcol) = __halves2bfloat162(
                __float2bfloat16(p2 - __bfloat162float(h2)),
                __float2bfloat16(p3 - __bfloat162float(h3)));
        }
        l0 += __shfl_xor_sync(0xffffffffu, l0, 1);
        l0 += __shfl_xor_sync(0xffffffffu, l0, 2);
        l1 += __shfl_xor_sync(0xffffffffu, l1, 1);
        l1 += __shfl_xor_sync(0xffffffffu, l1, 2);
        if (cn == 0) {
            atomicAdd(&smls[wm * 16 + gr], l0);
            atomicAdd(&smls[wm * 16 + gr + 8], l1);
        }

        CP_WAIT0();          // V ready (K_next not yet committed)
        __syncthreads();     // P visible; K-buffer reads done

        // prefetch NEXT K tile (hides behind probs writeback + PV)
        if (kt0 + 64 <= q0) {
#pragma unroll
            for (int i = 0; i < 8; i++) {
                int seg = tid + i * 256;
                int r = seg >> 5, s = seg & 31;
                size_t g = ((size_t)(b * S_LEN + kt0 + 64 + r)) * 1024 +
                           hkv * 256 + s * 8;
                cp_async16(sb + SM_KH + r * DP + s * 16, kh + g);
                cp_async16(sb + SM_KL + r * DP + s * 16, kl + g);
            }
            CP_COMMIT();
        }

        // ---- coalesced probs writeback from smem P (hi+lo) ----
#pragma unroll
        for (int i = 0; i < 4; i++) {
            int idx = tid + i * 256;
            int r = idx >> 4;
            int c4 = (idx & 15) * 4;
            uint2 vh2 = *(const uint2*)(smem + SM_PH + r * PP + c4 * 2);
            uint2 vl2 = *(const uint2*)(smem + SM_PL + r * PP + c4 * 2);
            float2 a0 = __bfloat1622float2(*(__nv_bfloat162*)&vh2.x);
            float2 a1 = __bfloat1622float2(*(__nv_bfloat162*)&vh2.y);
            float2 b0 = __bfloat1622float2(*(__nv_bfloat162*)&vl2.x);
            float2 b1 = __bfloat1622float2(*(__nv_bfloat162*)&vl2.y);
            float4 pv;
            pv.x = a0.x + b0.x; pv.y = a0.y + b0.y;
            pv.z = a1.x + b1.x; pv.w = a1.y + b1.y;
            *(float4*)(probs + ((size_t)bh * S_LEN + q0 + r) * S_LEN + kt0 + c4) = pv;
        }

        // ---- O += P~ V ----
        const uint32_t pa = sb + SM_PH + (wm * 16 + (lane & 15)) * PP +
                            (lane >> 4) * 16;
        const uint32_t vb = sb + SM_VH + (lane & 15) * DP +
                            (wn * 128) * 2 + (lane >> 4) * 16;
#pragma unroll
        for (int kk = 0; kk < 4; kk++) {
            uint32_t ph[4], pl[4];
            ldsm_x4(ph, pa + kk * 32);
            ldsm_x4(pl, pa + (SM_PL - SM_PH) + kk * 32);
#pragma unroll
            for (int nj = 0; nj < 8; nj++) {
                uint32_t vbh[4], vbl[4];
                uint32_t va = vb + kk * (16 * DP) + nj * 32;
                ldsm_x4t(vbh, va);
                ldsm_x4t(vbl, va + (SM_VL - SM_VH));
                mma16816(acco[nj * 2], ph, vbh);
                mma16816(acco[nj * 2], ph, vbl);
                mma16816(acco[nj * 2], pl, vbh);
                mma16816(acco[nj * 2 + 1], ph, vbh + 2);
                mma16816(acco[nj * 2 + 1], ph, vbl + 2);
                mma16816(acco[nj * 2 + 1], pl, vbh + 2);
            }
        }
        // trailing sync elided: next iteration's CP_WAIT0 + __syncthreads
    }
    __syncthreads();

    // ---- final epilogue ----
    if (tid < 64)
        linv[(size_t)bh * S_LEN + q0 + tid] = 1.f / smls[tid];
    float inv0 = 1.f / smls[wm * 16 + gr];
    float inv1 = 1.f / smls[wm * 16 + gr + 8];
#pragma unroll
    for (int ni = 0; ni < 16; ni++) {
        int col = wn * 128 + ni * 8 + cn * 2;
        float o0 = acco[ni][0] * inv0, o1 = acco[ni][1] * inv0;
        float o2 = acco[ni][2] * inv1, o3 = acco[ni][3] * inv1;
        *(float2*)(attn_out + ((size_t)bh * S_LEN + qg0) * 256 + col) =
            make_float2(o0, o1);
        *(float2*)(attn_out + ((size_t)bh * S_LEN + qg1) * 256 + col) =
            make_float2(o2, o3);
        size_t ga0 = ((size_t)(b * S_LEN) + qg0) * 2048 + h * 256 + col;
        size_t ga1 = ((size_t)(b * S_LEN) + qg1) * 2048 + h * 256 + col;
        __nv_bfloat16 h0 = __float2bfloat16(o0), h1 = __float2bfloat16(o1);
        __nv_bfloat16 h2 = __float2bfloat16(o2), h3 = __float2bfloat16(o3);
        *(__nv_bfloat162*)(gath + ga0) = __halves2bfloat162(h0, h1);
        *(__nv_bfloat162*)(gath + ga1) = __halves2bfloat162(h2, h3);
        *(__nv_bfloat162*)(gatl + ga0) = __halves2bfloat162(
            __float2bfloat16(o0 - __bfloat162float(h0)),
            __float2bfloat16(o1 - __bfloat162float(h1)));
        *(__nv_bfloat162*)(gatl + ga1) = __halves2bfloat162(
            __float2bfloat16(o2 - __bfloat162float(h2)),
            __float2bfloat16(o3 - __bfloat162float(h3)));
    }
}

// =====================================================================
// Full-row probs finalize: zero outside the band, scale inside.
// =====================================================================
__global__ void norm_probs_full(float* __restrict__ probs,
                                const float* __restrict__ linv)
{
    int row = blockIdx.x;
    int i = row & (S_LEN - 1);
    float inv = linv[row];
    int lo = max(0, i - 1023);
    float4* p = (float4*)(probs + (size_t)row * S_LEN);
#pragma unroll
    for (int c = (int)threadIdx.x; c < 512; c += 256) {
        int c0 = c << 2;
        float4 v;
        if (c0 + 3 < lo || c0 > i) {
            v = make_float4(0.f, 0.f, 0.f, 0.f);
        } else {
            v = p[c];
            v.x = (c0 >= lo && c0 <= i)         ? v.x * inv : 0.f;
            v.y = (c0 + 1 >= lo && c0 + 1 <= i) ? v.y * inv : 0.f;
            v.z = (c0 + 2 >= lo && c0 + 2 <= i) ? v.z * inv : 0.f;
            v.w = (c0 + 3 >= lo && c0 + 3 <= i) ? v.w * inv : 0.f;
        }
        p[c] = v;
    }
}

// =====================================================================
// Outputs: out[2,2048,2048] @0 | probs @8388608 | attn @75497472
// Stream fork/join (capture-legal, validated R10/R11).
// =====================================================================
extern "C" void kernel_launch(void* const* d_in, const int* in_sizes, int n_in,
                              void* d_out, int out_size)
{
    const float* hs = (const float*)d_in[0];
    const float* fc = (const float*)d_in[1];
    const float* fs = (const float*)d_in[2];
    const float* wq = (const float*)d_in[4];
    const float* wk = (const float*)d_in[5];
    const float* wv = (const float*)d_in[6];
    const float* wo = (const float*)d_in[7];

    float* out   = (float*)d_out;
    float* probs = out + 8388608ull;
    float* attn  = probs + 67108864ull;

    float *gqkv, *glinv;
    cudaGetSymbolAddress((void**)&gqkv, g_qkv);
    cudaGetSymbolAddress((void**)&glinv, g_linv);

    void *hsh, *hsl, *atth, *attl, *wh, *wl, *woh, *wol;
    void *qh, *ql, *kh, *kl, *vh, *vl;
    cudaGetSymbolAddress(&hsh, g_hs_h);  cudaGetSymbolAddress(&hsl, g_hs_l);
    cudaGetSymbolAddress(&atth, g_att_h); cudaGetSymbolAddress(&attl, g_att_l);
    cudaGetSymbolAddress(&wh, g_w_h);    cudaGetSymbolAddress(&wl, g_w_l);
    cudaGetSymbolAddress(&woh, g_wo_h);  cudaGetSymbolAddress(&wol, g_wo_l);
    cudaGetSymbolAddress(&qh, g_qh);     cudaGetSymbolAddress(&ql, g_ql);
    cudaGetSymbolAddress(&kh, g_kh);     cudaGetSymbolAddress(&kl, g_kl);
    cudaGetSymbolAddress(&vh, g_vh);     cudaGetSymbolAddress(&vl, g_vl);

    cudaFuncSetAttribute(gemm_hmma,
                         cudaFuncAttributeMaxDynamicSharedMemorySize, GEMM_SMEM);
    cudaFuncSetAttribute(attn_hmma,
                         cudaFuncAttributeMaxDynamicSharedMemorySize, ATT_SMEM);

    static cudaStream_t s1 = nullptr;
    static cudaEvent_t eStart, eW, eWo, eGemm, eP, eAtt, eNorm;
    if (!s1) {
        cudaStreamCreateWithFlags(&s1, cudaStreamNonBlocking);
        cudaEventCreateWithFlags(&eStart, cudaEventDisableTiming);
        cudaEventCreateWithFlags(&eW,     cudaEventDisableTiming);
        cudaEventCreateWithFlags(&eWo,    cudaEventDisableTiming);
        cudaEventCreateWithFlags(&eGemm,  cudaEventDisableTiming);
        cudaEventCreateWithFlags(&eP,     cudaEventDisableTiming);
        cudaEventCreateWithFlags(&eAtt,   cudaEventDisableTiming);
        cudaEventCreateWithFlags(&eNorm,  cudaEventDisableTiming);
    }

    __nv_bfloat16* whb = (__nv_bfloat16*)wh;
    __nv_bfloat16* wlb = (__nv_bfloat16*)wl;

    // fork: side stream handles weight splits while main does hs split
    cudaEventRecord(eStart, 0);
    cudaStreamWaitEvent(s1, eStart, 0);

    split_kernel<<<8192, 256>>>(hs, (__nv_bfloat16*)hsh, (__nv_bfloat16*)hsl,
                                2097152);

    split_kernel<<<4096, 256, 0, s1>>>(wq, whb, wlb, 1048576);
    split_kernel<<<2048, 256, 0, s1>>>(wk, whb + 2048ull * 2048,
                                       wlb + 2048ull * 2048, 524288);
    split_kernel<<<2048, 256, 0, s1>>>(wv, whb + 3072ull * 2048,
                                       wlb + 3072ull * 2048, 524288);
    cudaEventRecord(eW, s1);
    split_kernel<<<4096, 256, 0, s1>>>(wo, (__nv_bfloat16*)woh,
                                       (__nv_bfloat16*)wol, 1048576);
    cudaEventRecord(eWo, s1);

    // main: QKV GEMM
    cudaStreamWaitEvent(0, eW, 0);
    gemm_hmma<<<dim3(32, 32), 256, GEMM_SMEM>>>(
        (const __nv_bfloat16*)hsh, (const __nv_bfloat16*)hsl,
        whb, wlb, gqkv, 4096, 4096, 2048);
    cudaEventRecord(eGemm, 0);

    // fork: rope_k + v split on s1, rope_q on main
    cudaStreamWaitEvent(s1, eGemm, 0);
    rope_split_kernel<<<8192, 256, 0, s1>>>(gqkv, 2048, fc, fs,
                                            (__nv_bfloat16*)kh,
                                            (__nv_bfloat16*)kl, 4, 1.0f);
    split_strided_kernel<<<4096, 256, 0, s1>>>(gqkv, 3072, (__nv_bfloat16*)vh,
                                               (__nv_bfloat16*)vl);
    cudaEventRecord(eP, s1);

    rope_split_kernel<<<16384, 256>>>(gqkv, 0, fc, fs, (__nv_bfloat16*)qh,
                                      (__nv_bfloat16*)ql, 8, QSCALE);
    cudaStreamWaitEvent(0, eP, 0);

    // attention on main
    attn_hmma<<<dim3(32, 8, 2), 256, ATT_SMEM>>>(
        (const __nv_bfloat16*)qh, (const __nv_bfloat16*)ql,
        (const __nv_bfloat16*)kh, (const __nv_bfloat16*)kl,
        (const __nv_bfloat16*)vh, (const __nv_bfloat16*)vl,
        probs, attn, (__nv_bfloat16*)atth, (__nv_bfloat16*)attl, glinv);
    cudaEventRecord(eAtt, 0);

    // fork: probs normalize on s1, concurrent with wo GEMM on main
    cudaStreamWaitEvent(s1, eAtt, 0);
    norm_probs_full<<<32768, 256, 0, s1>>>(probs, glinv);
    cudaEventRecord(eNorm, s1);

    cudaStreamWaitEvent(0, eWo, 0);
    gemm_hmma<<<dim3(16, 32), 256, GEMM_SMEM>>>(
        (const __nv_bfloat16*)atth, (const __nv_bfloat16*)attl,
        (const __nv_bfloat16*)woh, (const __nv_bfloat16*)wol, out,
        4096, 2048, 2048);

    // join side stream back into main before returning
    cudaStreamWaitEvent(0, eNorm, 0);
}

// round 14
// speedup vs baseline: 1.1505x; 1.0023x over previous
#include <cuda_runtime.h>
#include <cuda_bf16.h>
#include <math.h>
#include <stdint.h>

#define S_LEN 2048
#define HID   2048
#define NH    8
#define NKV   4
#define HD    256
#define QSCALE 0.0625f       // D^-0.5
#define INV_CAP 0.02f        // 1/50
#define CAP    50.0f

// ---- fp32 scratch ----
__device__ float g_qkv[(size_t)4096 * 4096];   // q cols 0-2047 | k 2048-3071 | v 3072-4095
__device__ float g_linv[32768];

// ---- bf16 split scratch ----
__device__ uint4 g_hs_h[(size_t)4096 * 2048 / 8];
__device__ uint4 g_hs_l[(size_t)4096 * 2048 / 8];
__device__ uint4 g_att_h[(size_t)4096 * 2048 / 8];
__device__ uint4 g_att_l[(size_t)4096 * 2048 / 8];
__device__ uint4 g_w_h[(size_t)4096 * 2048 / 8];   // wq rows 0-2047 | wk | wv
__device__ uint4 g_w_l[(size_t)4096 * 2048 / 8];
__device__ uint4 g_wo_h[(size_t)2048 * 2048 / 8];
__device__ uint4 g_wo_l[(size_t)2048 * 2048 / 8];
__device__ uint4 g_qh[(size_t)4096 * 2048 / 8];
__device__ uint4 g_ql[(size_t)4096 * 2048 / 8];
__device__ uint4 g_kh[(size_t)4096 * 1024 / 8];
__device__ uint4 g_kl[(size_t)4096 * 1024 / 8];
__device__ uint4 g_vh[(size_t)4096 * 1024 / 8];
__device__ uint4 g_vl[(size_t)4096 * 1024 / 8];

// =====================================================================
// helpers
// =====================================================================
__device__ __forceinline__ uint32_t smem_u32(const void* p) {
    uint32_t a;
    asm("{ .reg .u64 t; cvta.to.shared.u64 t, %1; cvt.u32.u64 %0, t; }"
        : "=r"(a) : "l"(p));
    return a;
}
__device__ __forceinline__ void cp_async16(uint32_t saddr, const void* gaddr) {
    asm volatile("cp.async.cg.shared.global [%0], [%1], 16;"
                 :: "r"(saddr), "l"(gaddr) : "memory");
}
#define CP_COMMIT() asm volatile("cp.async.commit_group;" ::: "memory")
#define CP_WAIT1()  asm volatile("cp.async.wait_group 1;" ::: "memory")
#define CP_WAIT0()  asm volatile("cp.async.wait_group 0;" ::: "memory")

__device__ __forceinline__ void ldsm_x4(uint32_t* r, uint32_t addr) {
    asm volatile("ldmatrix.sync.aligned.m8n8.x4.shared.b16 {%0,%1,%2,%3}, [%4];"
                 : "=r"(r[0]), "=r"(r[1]), "=r"(r[2]), "=r"(r[3]) : "r"(addr));
}
__device__ __forceinline__ void ldsm_x4t(uint32_t* r, uint32_t addr) {
    asm volatile("ldmatrix.sync.aligned.m8n8.x4.trans.shared.b16 {%0,%1,%2,%3}, [%4];"
                 : "=r"(r[0]), "=r"(r[1]), "=r"(r[2]), "=r"(r[3]) : "r"(addr));
}
__device__ __forceinline__ void ldsm_x2(uint32_t* r, uint32_t addr) {
    asm volatile("ldmatrix.sync.aligned.m8n8.x2.shared.b16 {%0,%1}, [%2];"
                 : "=r"(r[0]), "=r"(r[1]) : "r"(addr));
}
__device__ __forceinline__ void mma16816(float* c, const uint32_t* a,
                                         const uint32_t* b) {
    asm volatile(
        "mma.sync.aligned.m16n8k16.row.col.f32.bf16.bf16.f32 "
        "{%0,%1,%2,%3}, {%4,%5,%6,%7}, {%8,%9}, {%0,%1,%2,%3};"
        : "+f"(c[0]), "+f"(c[1]), "+f"(c[2]), "+f"(c[3])
        : "r"(a[0]), "r"(a[1]), "r"(a[2]), "r"(a[3]), "r"(b[0]), "r"(b[1]));
}

// =====================================================================
// split fp32 -> (hi, lo) bf16  (contiguous)
// =====================================================================
__global__ void split_kernel(const float* __restrict__ x,
                             __nv_bfloat16* __restrict__ hi,
                             __nv_bfloat16* __restrict__ lo, int n4)
{
    int i = blockIdx.x * blockDim.x + threadIdx.x;
    if (i >= n4) return;
    float4 v = ((const float4*)x)[i];
    __nv_bfloat16 h0 = __float2bfloat16(v.x);
    __nv_bfloat16 h1 = __float2bfloat16(v.y);
    __nv_bfloat16 h2 = __float2bfloat16(v.z);
    __nv_bfloat16 h3 = __float2bfloat16(v.w);
    __nv_bfloat16 l0 = __float2bfloat16(v.x - __bfloat162float(h0));
    __nv_bfloat16 l1 = __float2bfloat16(v.y - __bfloat162float(h1));
    __nv_bfloat16 l2 = __float2bfloat16(v.z - __bfloat162float(h2));
    __nv_bfloat16 l3 = __float2bfloat16(v.w - __bfloat162float(h3));
    __nv_bfloat162* h2p = (__nv_bfloat162*)hi;
    __nv_bfloat162* l2p = (__nv_bfloat162*)lo;
    h2p[2 * i]     = __halves2bfloat162(h0, h1);
    h2p[2 * i + 1] = __halves2bfloat162(h2, h3);
    l2p[2 * i]     = __halves2bfloat162(l0, l1);
    l2p[2 * i + 1] = __halves2bfloat162(l2, l3);
}

// =====================================================================
// split fp32 submatrix (row stride 4096, col offset) -> bf16 hi/lo [., 1024]
// =====================================================================
__global__ void split_strided_kernel(const float* __restrict__ x, int coloff,
                                     __nv_bfloat16* __restrict__ hi,
                                     __nv_bfloat16* __restrict__ lo)
{
    int i = blockIdx.x * blockDim.x + threadIdx.x;
    if (i >= 4096 * 256) return;
    int row = i >> 8, c4 = (i & 255) << 2;
    float4 v = *(const float4*)(x + (size_t)row * 4096 + coloff + c4);
    __nv_bfloat16 h0 = __float2bfloat16(v.x);
    __nv_bfloat16 h1 = __float2bfloat16(v.y);
    __nv_bfloat16 h2 = __float2bfloat16(v.z);
    __nv_bfloat16 h3 = __float2bfloat16(v.w);
    size_t o = (size_t)row * 1024 + c4;
    *(__nv_bfloat162*)(hi + o)     = __halves2bfloat162(h0, h1);
    *(__nv_bfloat162*)(hi + o + 2) = __halves2bfloat162(h2, h3);
    *(__nv_bfloat162*)(lo + o)     = __halves2bfloat162(
        __float2bfloat16(v.x - __bfloat162float(h0)),
        __float2bfloat16(v.y - __bfloat162float(h1)));
    *(__nv_bfloat162*)(lo + o + 2) = __halves2bfloat162(
        __float2bfloat16(v.z - __bfloat162float(h2)),
        __float2bfloat16(v.w - __bfloat162float(h3)));
}

// =====================================================================
// RoPE + scale + bf16 split; input row stride 4096 with column offset
// =====================================================================
__global__ void rope_split_kernel(const float* __restrict__ buf, int coloff,
                                  const float* __restrict__ cosb,
                                  const float* __restrict__ sinb,
                                  __nv_bfloat16* __restrict__ oh,
                                  __nv_bfloat16* __restrict__ ol,
                                  int nheads, float scale)
{
    int idx = blockIdx.x * blockDim.x + threadIdx.x;
    int total = 4096 * nheads * 128;
    if (idx >= total) return;
    int j = idx & 127;
    int h = (idx >> 7) % nheads;
    int n = idx / (128 * nheads);
    int t = n & (S_LEN - 1);
    size_t ibase = (size_t)n * 4096 + coloff + h * 256 + j;
    size_t obase = (size_t)n * (nheads * 256) + h * 256 + j;
    float x1 = buf[ibase];
    float x2 = buf[ibase + 128];
    float c = cosb[t * 128 + j];
    float s = sinb[t * 128 + j];
    float y1 = (x1 * c - x2 * s) * scale;
    float y2 = (x1 * s + x2 * c) * scale;
    __nv_bfloat16 h1 = __float2bfloat16(y1);
    __nv_bfloat16 h2v = __float2bfloat16(y2);
    oh[obase]       = h1;
    oh[obase + 128] = h2v;
    ol[obase]       = __float2bfloat16(y1 - __bfloat162float(h1));
    ol[obase + 128] = __float2bfloat16(y2 - __bfloat162float(h2v));
}

// =====================================================================
// HMMA GEMM: 128x128 tile, K-chunk 32, 2-stage, 2 CTAs/SM.
// Single sync per K-iteration: wait -> sync -> issue(c+1) -> compute(c).
// issue(c+1) writes buffer (c-1)&1, whose readers all passed this sync.
// =====================================================================
#define STAGES 2
#define TILE_B 10240
#define STAGE_B (4 * TILE_B)
#define GEMM_SMEM (STAGES * STAGE_B)   // 81920

__device__ __forceinline__ void issue_stage(
    uint32_t sb, int c, int tid, int m0, int n0, int K,
    const __nv_bfloat16* Ah, const __nv_bfloat16* Al,
    const __nv_bfloat16* Bh, const __nv_bfloat16* Bl)
{
    uint32_t st = sb + (uint32_t)(c & 1) * STAGE_B;
    int k0 = c * 32;
#pragma unroll
    for (int half = 0; half < 2; half++) {
        int idx = tid + half * 256;
        int row = idx >> 2;
        int seg = idx & 3;
        uint32_t so = (uint32_t)(row * 80 + seg * 16);
        size_t ga = (size_t)(m0 + row) * K + k0 + seg * 8;
        size_t gb = (size_t)(n0 + row) * K + k0 + seg * 8;
        cp_async16(st + so,              Ah + ga);
        cp_async16(st + TILE_B + so,     Al + ga);
        cp_async16(st + 2 * TILE_B + so, Bh + gb);
        cp_async16(st + 3 * TILE_B + so, Bl + gb);
    }
    CP_COMMIT();
}

__global__ __launch_bounds__(256, 2) void gemm_hmma(
    const __nv_bfloat16* __restrict__ Ah, const __nv_bfloat16* __restrict__ Al,
    const __nv_bfloat16* __restrict__ Bh, const __nv_bfloat16* __restrict__ Bl,
    float* __restrict__ C, int M, int N, int K)
{
    extern __shared__ __align__(128) char smem[];
    const uint32_t sb = smem_u32(smem);
    const int tid = threadIdx.x;
    const int wid = tid >> 5, lane = tid & 31;
    const int wm = wid >> 2, wn = wid & 3;
    const int m0 = blockIdx.y * 128, n0 = blockIdx.x * 128;

    float acc[4][4][4];
#pragma unroll
    for (int mi = 0; mi < 4; mi++)
#pragma unroll
        for (int ni = 0; ni < 4; ni++)
#pragma unroll
            for (int r = 0; r < 4; r++) acc[mi][ni][r] = 0.f;

    const int NC = K >> 5;
    issue_stage(sb, 0, tid, m0, n0, K, Ah, Al, Bh, Bl);

    const uint32_t aoff = (uint32_t)((wm * 64 + (lane & 15)) * 80 +
                                     (lane >> 4) * 16);
    const uint32_t boff = (uint32_t)((wn * 32 + (lane & 7)) * 80 +
                                     ((lane >> 3) & 1) * 16);

    for (int c = 0; c < NC; c++) {
        CP_WAIT0();          // stage c loaded (only pending group)
        __syncthreads();     // all warps done with compute(c-1) AND see stage c
        if (c + 1 < NC)
            issue_stage(sb, c + 1, tid, m0, n0, K, Ah, Al, Bh, Bl);
        const uint32_t st = sb + (uint32_t)(c & 1) * STAGE_B;
        const uint32_t aA = st + aoff;
        const uint32_t aB = st + 2 * TILE_B + boff;

#pragma unroll
        for (int ks = 0; ks < 2; ks++) {
            uint32_t ah[4][4], al[4][4], bh[4][2], bl[4][2];
#pragma unroll
            for (int mi = 0; mi < 4; mi++)
                ldsm_x4(ah[mi], aA + mi * (16 * 80) + ks * 32);
#pragma unroll
            for (int ni = 0; ni < 4; ni++) {
                ldsm_x2(bh[ni], aB + ni * (8 * 80) + ks * 32);
                ldsm_x2(bl[ni], aB + TILE_B + ni * (8 * 80) + ks * 32);
            }
#pragma unroll
            for (int mi = 0; mi < 4; mi++)
#pragma unroll
                for (int ni = 0; ni < 4; ni++) {
                    mma16816(acc[mi][ni], ah[mi], bh[ni]);
                    mma16816(acc[mi][ni], ah[mi], bl[ni]);
                }
#pragma unroll
            for (int mi = 0; mi < 4; mi++)
                ldsm_x4(al[mi], aA + TILE_B + mi * (16 * 80) + ks * 32);
#pragma unroll
            for (int mi = 0; mi < 4; mi++)
#pragma unroll
                for (int ni = 0; ni < 4; ni++)
                    mma16816(acc[mi][ni], al[mi], bh[ni]);
        }
        // no trailing sync: next iteration's wait+sync protects buffer reuse
    }

    const int gr = lane >> 2, cn = lane & 3;
#pragma unroll
    for (int mi = 0; mi < 4; mi++) {
        int r = m0 + wm * 64 + mi * 16 + gr;
#pragma unroll
        for (int ni = 0; ni < 4; ni++) {
            int col = n0 + wn * 32 + ni * 8 + cn * 2;
            *(float2*)(C + (size_t)r * N + col) =
                make_float2(acc[mi][ni][0], acc[mi][ni][1]);
            *(float2*)(C + (size_t)(r + 8) * N + col) =
                make_float2(acc[mi][ni][2], acc[mi][ni][3]);
        }
    }
}

// =====================================================================
// HMMA attention with K-tile prefetch (R11/R13 validated) + short capexp.
// =====================================================================
#define DP 528
#define PP 144
#define SM_QH 0
#define SM_QL (64 * DP)
#define SM_KH (2 * 64 * DP)
#define SM_KL (3 * 64 * DP)
#define SM_VH (4 * 64 * DP)
#define SM_VL (5 * 64 * DP)
#define SM_PH (6 * 64 * DP)
#define SM_PL (SM_PH + 64 * PP)
#define SM_LS (SM_PL + 64 * PP)
#define ATT_SMEM (SM_LS + 256)

__device__ __forceinline__ float capexp(float s, int ig, int jg) {
    float x = s * INV_CAP;
    x = fminf(fmaxf(x, -15.f), 15.f);
    float e = __expf(2.f * x);
    bool win = (jg <= ig) && (ig - jg < 1024);
    // p = exp(50*tanh(x) - 50) = exp(-100/(e+1))
    return win ? __expf(__fdividef(-100.f, e + 1.f)) : 0.f;
}

__global__ __launch_bounds__(256, 1) void attn_hmma(
    const __nv_bfloat16* __restrict__ qh, const __nv_bfloat16* __restrict__ ql,
    const __nv_bfloat16* __restrict__ kh, const __nv_bfloat16* __restrict__ kl,
    const __nv_bfloat16* __restrict__ vh, const __nv_bfloat16* __restrict__ vl,
    float* __restrict__ probs, float* __restrict__ attn_out,
    __nv_bfloat16* __restrict__ gath, __nv_bfloat16* __restrict__ gatl,
    float* __restrict__ linv)
{
    extern __shared__ __align__(128) char smem[];
    const uint32_t sb = smem_u32(smem);
    float* smls = (float*)(smem + SM_LS);
    const int tid = threadIdx.x, wid = tid >> 5, lane = tid & 31;
    const int wm = wid >> 1, wn = wid & 1;
    const int gr = lane >> 2, cn = lane & 3;
    const int q0 = (gridDim.x - 1 - blockIdx.x) * 64;
    const int h = blockIdx.y, b = blockIdx.z;
    const int hkv = h >> 1, bh = b * NH + h;

    const int kstart = max(0, q0 - 1024);

    // prologue: Q tile + first K tile in one cp.async group
#pragma unroll
    for (int i = 0; i < 8; i++) {
        int seg = tid + i * 256;
        int r = seg >> 5, s = seg & 31;
        size_t g = ((size_t)(b * S_LEN + q0 + r)) * 2048 + h * 256 + s * 8;
        cp_async16(sb + SM_QH + r * DP + s * 16, qh + g);
        cp_async16(sb + SM_QL + r * DP + s * 16, ql + g);
    }
#pragma unroll
    for (int i = 0; i < 8; i++) {
        int seg = tid + i * 256;
        int r = seg >> 5, s = seg & 31;
        size_t g = ((size_t)(b * S_LEN + kstart + r)) * 1024 + hkv * 256 + s * 8;
        cp_async16(sb + SM_KH + r * DP + s * 16, kh + g);
        cp_async16(sb + SM_KL + r * DP + s * 16, kl + g);
    }
    CP_COMMIT();
    if (tid < 64) smls[tid] = 0.f;

    float acco[16][4];
#pragma unroll
    for (int i = 0; i < 16; i++)
#pragma unroll
        for (int r = 0; r < 4; r++) acco[i][r] = 0.f;

    const int qg0 = q0 + wm * 16 + gr;
    const int qg1 = qg0 + 8;

    for (int kt0 = kstart; kt0 <= q0; kt0 += 64) {
        CP_WAIT0();          // K_kt ready (prologue or prefetched last iter)
        __syncthreads();     // also: all prior PV reads of V/P are done

        // issue V_kt (hides behind S compute)
#pragma unroll
        for (int i = 0; i < 8; i++) {
            int seg = tid + i * 256;
            int r = seg >> 5, s = seg & 31;
            size_t g = ((size_t)(b * S_LEN + kt0 + r)) * 1024 + hkv * 256 + s * 8;
            cp_async16(sb + SM_VH + r * DP + s * 16, vh + g);
            cp_async16(sb + SM_VL + r * DP + s * 16, vl + g);
        }
        CP_COMMIT();

        // ---- S = Q K^T ----
        float sacc[4][4];
#pragma unroll
        for (int ni = 0; ni < 4; ni++)
#pragma unroll
            for (int r = 0; r < 4; r++) sacc[ni][r] = 0.f;

        const uint32_t qa = sb + SM_QH + (wm * 16 + (lane & 15)) * DP +
                            (lane >> 4) * 16;
        const uint32_t kb = sb + SM_KH + (wn * 32 + (lane & 7)) * DP +
                            ((lane >> 3) & 1) * 16;
#pragma unroll 4
        for (int kc = 0; kc < 16; kc++) {
            uint32_t ah[4], al[4], bhf[4][2], blf[4][2];
            ldsm_x4(ah, qa + kc * 32);
            ldsm_x4(al, qa + (SM_QL - SM_QH) + kc * 32);
#pragma unroll
            for (int ni = 0; ni < 4; ni++) {
                ldsm_x2(bhf[ni], kb + ni * (8 * DP) + kc * 32);
                ldsm_x2(blf[ni], kb + (SM_KL - SM_KH) + ni * (8 * DP) + kc * 32);
            }
#pragma unroll
            for (int ni = 0; ni < 4; ni++) {
                mma16816(sacc[ni], ah, bhf[ni]);
                mma16816(sacc[ni], ah, blf[ni]);
                mma16816(sacc[ni], al, bhf[ni]);
            }
        }

        // ---- softcap/exp, P split into smem, row sums ----
        float l0 = 0.f, l1 = 0.f;
#pragma unroll
        for (int ni = 0; ni < 4; ni++) {
            int keyb = kt0 + wn * 32 + ni * 8 + cn * 2;
            float p0 = capexp(sacc[ni][0], qg0, keyb);
            float p1 = capexp(sacc[ni][1], qg0, keyb + 1);
            float p2 = capexp(sacc[ni][2], qg1, keyb);
            float p3 = capexp(sacc[ni][3], qg1, keyb + 1);
            l0 += p0 + p1;
            l1 += p2 + p3;
            __nv_bfloat16 h0 = __float2bfloat16(p0), h1 = __float2bfloat16(p1);
            __nv_bfloat16 h2 = __float2bfloat16(p2), h3 = __float2bfloat16(p3);
            int pcol = (wn * 32 + ni * 8 + cn * 2) * 2;
            int pr0 = (wm * 16 + gr) * PP, pr1 = pr0 + 8 * PP;
            *(__nv_bfloat162*)(smem + SM_PH + pr0 + pcol) = __halves2bfloat162(h0, h1);
            *(__nv_bfloat162*)(smem + SM_PH + pr1 + pcol) = __halves2bfloat162(h2, h3);
            *(__nv_bfloat162*)(smem + SM_PL + pr0 + pcol) = __halves2bfloat162(
                __float2bfloat16(p0 - __bfloat162float(h0)),
                __float2bfloat16(p1 - __bfloat162float(h1)));
            *(__nv_bfloat162*)(smem + SM_PL + pr1 + pcol) = __halves2bfloat162(
                __float2bfloat16(p2 - __bfloat162float(h2)),
                __float2bfloat16(p3 - __bfloat162float(h3)));
        }
        l0 += __shfl_xor_sync(0xffffffffu, l0, 1);
        l0 += __shfl_xor_sync(0xffffffffu, l0, 2);
        l1 += __shfl_xor_sync(0xffffffffu, l1, 1);
        l1 += __shfl_xor_sync(0xffffffffu, l1, 2);
        if (cn == 0) {
            atomicAdd(&smls[wm * 16 + gr], l0);
            atomicAdd(&smls[wm * 16 + gr + 8], l1);
        }

        CP_WAIT0();          // V ready (K_next not yet committed)
        __syncthreads();     // P visible; K-buffer reads done

        // prefetch NEXT K tile (hides behind probs writeback + PV)
        if (kt0 + 64 <= q0) {
#pragma unroll
            for (int i = 0; i < 8; i++) {
                int seg = tid + i * 256;
                int r = seg >> 5, s = seg & 31;
                size_t g = ((size_t)(b * S_LEN + kt0 + 64 + r)) * 1024 +
                           hkv * 256 + s * 8;
                cp_async16(sb + SM_KH + r * DP + s * 16, kh + g);
                cp_async16(sb + SM_KL + r * DP + s * 16, kl + g);
            }
            CP_COMMIT();
        }

        // ---- coalesced probs writeback from smem P (hi+lo) ----
#pragma unroll
        for (int i = 0; i < 4; i++) {
            int idx = tid + i * 256;
            int r = idx >> 4;
            int c4 = (idx & 15) * 4;
            uint2 vh2 = *(const uint2*)(smem + SM_PH + r * PP + c4 * 2);
            uint2 vl2 = *(const uint2*)(smem + SM_PL + r * PP + c4 * 2);
            float2 a0 = __bfloat1622float2(*(__nv_bfloat162*)&vh2.x);
            float2 a1 = __bfloat1622float2(*(__nv_bfloat162*)&vh2.y);
            float2 b0 = __bfloat1622float2(*(__nv_bfloat162*)&vl2.x);
            float2 b1 = __bfloat1622float2(*(__nv_bfloat162*)&vl2.y);
            float4 pv;
            pv.x = a0.x + b0.x; pv.y = a0.y + b0.y;
            pv.z = a1.x + b1.x; pv.w = a1.y + b1.y;
            *(float4*)(probs + ((size_t)bh * S_LEN + q0 + r) * S_LEN + kt0 + c4) = pv;
        }

        // ---- O += P~ V ----
        const uint32_t pa = sb + SM_PH + (wm * 16 + (lane & 15)) * PP +
                            (lane >> 4) * 16;
        const uint32_t vb = sb + SM_VH + (lane & 15) * DP +
                            (wn * 128) * 2 + (lane >> 4) * 16;
#pragma unroll
        for (int kk = 0; kk < 4; kk++) {
            uint32_t ph[4], pl[4];
            ldsm_x4(ph, pa + kk * 32);
            ldsm_x4(pl, pa + (SM_PL - SM_PH) + kk * 32);
#pragma unroll
            for (int nj = 0; nj < 8; nj++) {
                uint32_t vbh[4], vbl[4];
                uint32_t va = vb + kk * (16 * DP) + nj * 32;
                ldsm_x4t(vbh, va);
                ldsm_x4t(vbl, va + (SM_VL - SM_VH));
                mma16816(acco[nj * 2], ph, vbh);
                mma16816(acco[nj * 2], ph, vbl);
                mma16816(acco[nj * 2], pl, vbh);
                mma16816(acco[nj * 2 + 1], ph, vbh + 2);
                mma16816(acco[nj * 2 + 1], ph, vbl + 2);
                mma16816(acco[nj * 2 + 1], pl, vbh + 2);
            }
        }
        // trailing sync elided: next iteration's CP_WAIT0 + __syncthreads
    }
    __syncthreads();

    // ---- final epilogue ----
    if (tid < 64)
        linv[(size_t)bh * S_LEN + q0 + tid] = 1.f / smls[tid];
    float inv0 = 1.f / smls[wm * 16 + gr];
    float inv1 = 1.f / smls[wm * 16 + gr + 8];
#pragma unroll
    for (int ni = 0; ni < 16; ni++) {
        int col = wn * 128 + ni * 8 + cn * 2;
        float o0 = acco[ni][0] * inv0, o1 = acco[ni][1] * inv0;
        float o2 = acco[ni][2] * inv1, o3 = acco[ni][3] * inv1;
        *(float2*)(attn_out + ((size_t)bh * S_LEN + qg0) * 256 + col) =
            make_float2(o0, o1);
        *(float2*)(attn_out + ((size_t)bh * S_LEN + qg1) * 256 + col) =
            make_float2(o2, o3);
        size_t ga0 = ((size_t)(b * S_LEN) + qg0) * 2048 + h * 256 + col;
        size_t ga1 = ((size_t)(b * S_LEN) + qg1) * 2048 + h * 256 + col;
        __nv_bfloat16 h0 = __float2bfloat16(o0), h1 = __float2bfloat16(o1);
        __nv_bfloat16 h2 = __float2bfloat16(o2), h3 = __float2bfloat16(o3);
        *(__nv_bfloat162*)(gath + ga0) = __halves2bfloat162(h0, h1);
        *(__nv_bfloat162*)(gath + ga1) = __halves2bfloat162(h2, h3);
        *(__nv_bfloat162*)(gatl + ga0) = __halves2bfloat162(
            __float2bfloat16(o0 - __bfloat162float(h0)),
            __float2bfloat16(o1 - __bfloat162float(h1)));
        *(__nv_bfloat162*)(gatl + ga1) = __halves2bfloat162(
            __float2bfloat16(o2 - __bfloat162float(h2)),
            __float2bfloat16(o3 - __bfloat162float(h3)));
    }
}

// =====================================================================
// Full-row probs finalize: zero outside the band, scale inside.
// =====================================================================
__global__ void norm_probs_full(float* __restrict__ probs,
                                const float* __restrict__ linv)
{
    int row = blockIdx.x;
    int i = row & (S_LEN - 1);
    float inv = linv[row];
    int lo = max(0, i - 1023);
    float4* p = (float4*)(probs + (size_t)row * S_LEN);
#pragma unroll
    for (int c = (int)threadIdx.x; c < 512; c += 256) {
        int c0 = c << 2;
        float4 v;
        if (c0 + 3 < lo || c0 > i) {
            v = make_float4(0.f, 0.f, 0.f, 0.f);
        } else {
            v = p[c];
            v.x = (c0 >= lo && c0 <= i)         ? v.x * inv : 0.f;
            v.y = (c0 + 1 >= lo && c0 + 1 <= i) ? v.y * inv : 0.f;
            v.z = (c0 + 2 >= lo && c0 + 2 <= i) ? v.z * inv : 0.f;
            v.w = (c0 + 3 >= lo && c0 + 3 <= i) ? v.w * inv : 0.f;
        }
        p[c] = v;
    }
}

// =====================================================================
// Outputs: out[2,2048,2048] @0 | probs @8388608 | attn @75497472
// Stream fork/join (capture-legal, validated R10-R13).
// =====================================================================
extern "C" void kernel_launch(void* const* d_in, const int* in_sizes, int n_in,
                              void* d_out, int out_size)
{
    const float* hs = (const float*)d_in[0];
    const float* fc = (const float*)d_in[1];
    const float* fs = (const float*)d_in[2];
    const float* wq = (const float*)d_in[4];
    const float* wk = (const float*)d_in[5];
    const float* wv = (const float*)d_in[6];
    const float* wo = (const float*)d_in[7];

    float* out   = (float*)d_out;
    float* probs = out + 8388608ull;
    float* attn  = probs + 67108864ull;

    float *gqkv, *glinv;
    cudaGetSymbolAddress((void**)&gqkv, g_qkv);
    cudaGetSymbolAddress((void**)&glinv, g_linv);

    void *hsh, *hsl, *atth, *attl, *wh, *wl, *woh, *wol;
    void *qh, *ql, *kh, *kl, *vh, *vl;
    cudaGetSymbolAddress(&hsh, g_hs_h);  cudaGetSymbolAddress(&hsl, g_hs_l);
    cudaGetSymbolAddress(&atth, g_att_h); cudaGetSymbolAddress(&attl, g_att_l);
    cudaGetSymbolAddress(&wh, g_w_h);    cudaGetSymbolAddress(&wl, g_w_l);
    cudaGetSymbolAddress(&woh, g_wo_h);  cudaGetSymbolAddress(&wol, g_wo_l);
    cudaGetSymbolAddress(&qh, g_qh);     cudaGetSymbolAddress(&ql, g_ql);
    cudaGetSymbolAddress(&kh, g_kh);     cudaGetSymbolAddress(&kl, g_kl);
    cudaGetSymbolAddress(&vh, g_vh);     cudaGetSymbolAddress(&vl, g_vl);

    cudaFuncSetAttribute(gemm_hmma,
                         cudaFuncAttributeMaxDynamicSharedMemorySize, GEMM_SMEM);
    cudaFuncSetAttribute(attn_hmma,
                         cudaFuncAttributeMaxDynamicSharedMemorySize, ATT_SMEM);

    static cudaStream_t s1 = nullptr;
    static cudaEvent_t eStart, eW, eWo, eGemm, eP, eAtt, eNorm;
    if (!s1) {
        cudaStreamCreateWithFlags(&s1, cudaStreamNonBlocking);
        cudaEventCreateWithFlags(&eStart, cudaEventDisableTiming);
        cudaEventCreateWithFlags(&eW,     cudaEventDisableTiming);
        cudaEventCreateWithFlags(&eWo,    cudaEventDisableTiming);
        cudaEventCreateWithFlags(&eGemm,  cudaEventDisableTiming);
        cudaEventCreateWithFlags(&eP,     cudaEventDisableTiming);
        cudaEventCreateWithFlags(&eAtt,   cudaEventDisableTiming);
        cudaEventCreateWithFlags(&eNorm,  cudaEventDisableTiming);
    }

    __nv_bfloat16* whb = (__nv_bfloat16*)wh;
    __nv_bfloat16* wlb = (__nv_bfloat16*)wl;

    // fork: side stream handles weight splits while main does hs split
    cudaEventRecord(eStart, 0);
    cudaStreamWaitEvent(s1, eStart, 0);

    split_kernel<<<8192, 256>>>(hs, (__nv_bfloat16*)hsh, (__nv_bfloat16*)hsl,
                                2097152);

    split_kernel<<<4096, 256, 0, s1>>>(wq, whb, wlb, 1048576);
    split_kernel<<<2048, 256, 0, s1>>>(wk, whb + 2048ull * 2048,
                                       wlb + 2048ull * 2048, 524288);
    split_kernel<<<2048, 256, 0, s1>>>(wv, whb + 3072ull * 2048,
                                       wlb + 3072ull * 2048, 524288);
    cudaEventRecord(eW, s1);
    split_kernel<<<4096, 256, 0, s1>>>(wo, (__nv_bfloat16*)woh,
                                       (__nv_bfloat16*)wol, 1048576);
    cudaEventRecord(eWo, s1);

    // main: QKV GEMM
    cudaStreamWaitEvent(0, eW, 0);
    gemm_hmma<<<dim3(32, 32), 256, GEMM_SMEM>>>(
        (const __nv_bfloat16*)hsh, (const __nv_bfloat16*)hsl,
        whb, wlb, gqkv, 4096, 4096, 2048);
    cudaEventRecord(eGemm, 0);

    // fork: rope_k + v split on s1, rope_q on main
    cudaStreamWaitEvent(s1, eGemm, 0);
    rope_split_kernel<<<8192, 256, 0, s1>>>(gqkv, 2048, fc, fs,
                                            (__nv_bfloat16*)kh,
                                            (__nv_bfloat16*)kl, 4, 1.0f);
    split_strided_kernel<<<4096, 256, 0, s1>>>(gqkv, 3072, (__nv_bfloat16*)vh,
                                               (__nv_bfloat16*)vl);
    cudaEventRecord(eP, s1);

    rope_split_kernel<<<16384, 256>>>(gqkv, 0, fc, fs, (__nv_bfloat16*)qh,
                                      (__nv_bfloat16*)ql, 8, QSCALE);
    cudaStreamWaitEvent(0, eP, 0);

    // attention on main
    attn_hmma<<<dim3(32, 8, 2), 256, ATT_SMEM>>>(
        (const __nv_bfloat16*)qh, (const __nv_bfloat16*)ql,
        (const __nv_bfloat16*)kh, (const __nv_bfloat16*)kl,
        (const __nv_bfloat16*)vh, (const __nv_bfloat16*)vl,
        probs, attn, (__nv_bfloat16*)atth, (__nv_bfloat16*)attl, glinv);
    cudaEventRecord(eAtt, 0);

    // fork: probs normalize on s1, concurrent with wo GEMM on main
    cudaStreamWaitEvent(s1, eAtt, 0);
    norm_probs_full<<<32768, 256, 0, s1>>>(probs, glinv);
    cudaEventRecord(eNorm, s1);

    cudaStreamWaitEvent(0, eWo, 0);
    gemm_hmma<<<dim3(16, 32), 256, GEMM_SMEM>>>(
        (const __nv_bfloat16*)atth, (const __nv_bfloat16*)attl,
        (const __nv_bfloat16*)woh, (const __nv_bfloat16*)wol, out,
        4096, 2048, 2048);

    // join side stream back into main before returning
    cudaStreamWaitEvent(0, eNorm, 0);
}

// round 15
// speedup vs baseline: 1.1589x; 1.0073x over previous
#include <cuda_runtime.h>
#include <cuda_bf16.h>
#include <math.h>
#include <stdint.h>

#define S_LEN 2048
#define HID   2048
#define NH    8
#define NKV   4
#define HD    256
#define QSCALE 0.0625f       // D^-0.5
#define INV_CAP 0.02f        // 1/50
#define CAP    50.0f

// ---- fp32 scratch ----
__device__ float g_qkv[(size_t)4096 * 4096];   // q cols 0-2047 | k 2048-3071 | v 3072-4095
__device__ float g_linv[32768];

// ---- bf16 split scratch ----
__device__ uint4 g_hs_h[(size_t)4096 * 2048 / 8];
__device__ uint4 g_hs_l[(size_t)4096 * 2048 / 8];
__device__ uint4 g_att_h[(size_t)4096 * 2048 / 8];
__device__ uint4 g_att_l[(size_t)4096 * 2048 / 8];
__device__ uint4 g_w_h[(size_t)4096 * 2048 / 8];   // wq rows 0-2047 | wk | wv
__device__ uint4 g_w_l[(size_t)4096 * 2048 / 8];
__device__ uint4 g_wo_h[(size_t)2048 * 2048 / 8];
__device__ uint4 g_wo_l[(size_t)2048 * 2048 / 8];
__device__ uint4 g_kh[(size_t)4096 * 1024 / 8];
__device__ uint4 g_kl[(size_t)4096 * 1024 / 8];
__device__ uint4 g_vh[(size_t)4096 * 1024 / 8];
__device__ uint4 g_vl[(size_t)4096 * 1024 / 8];

// =====================================================================
// helpers
// =====================================================================
__device__ __forceinline__ uint32_t smem_u32(const void* p) {
    uint32_t a;
    asm("{ .reg .u64 t; cvta.to.shared.u64 t, %1; cvt.u32.u64 %0, t; }"
        : "=r"(a) : "l"(p));
    return a;
}
__device__ __forceinline__ void cp_async16(uint32_t saddr, const void* gaddr) {
    asm volatile("cp.async.cg.shared.global [%0], [%1], 16;"
                 :: "r"(saddr), "l"(gaddr) : "memory");
}
#define CP_COMMIT() asm volatile("cp.async.commit_group;" ::: "memory")
#define CP_WAIT1()  asm volatile("cp.async.wait_group 1;" ::: "memory")
#define CP_WAIT0()  asm volatile("cp.async.wait_group 0;" ::: "memory")

__device__ __forceinline__ void ldsm_x4(uint32_t* r, uint32_t addr) {
    asm volatile("ldmatrix.sync.aligned.m8n8.x4.shared.b16 {%0,%1,%2,%3}, [%4];"
                 : "=r"(r[0]), "=r"(r[1]), "=r"(r[2]), "=r"(r[3]) : "r"(addr));
}
__device__ __forceinline__ void ldsm_x4t(uint32_t* r, uint32_t addr) {
    asm volatile("ldmatrix.sync.aligned.m8n8.x4.trans.shared.b16 {%0,%1,%2,%3}, [%4];"
                 : "=r"(r[0]), "=r"(r[1]), "=r"(r[2]), "=r"(r[3]) : "r"(addr));
}
__device__ __forceinline__ void ldsm_x2(uint32_t* r, uint32_t addr) {
    asm volatile("ldmatrix.sync.aligned.m8n8.x2.shared.b16 {%0,%1}, [%2];"
                 : "=r"(r[0]), "=r"(r[1]) : "r"(addr));
}
__device__ __forceinline__ void mma16816(float* c, const uint32_t* a,
                                         const uint32_t* b) {
    asm volatile(
        "mma.sync.aligned.m16n8k16.row.col.f32.bf16.bf16.f32 "
        "{%0,%1,%2,%3}, {%4,%5,%6,%7}, {%8,%9}, {%0,%1,%2,%3};"
        : "+f"(c[0]), "+f"(c[1]), "+f"(c[2]), "+f"(c[3])
        : "r"(a[0]), "r"(a[1]), "r"(a[2]), "r"(a[3]), "r"(b[0]), "r"(b[1]));
}

// =====================================================================
// split fp32 -> (hi, lo) bf16  (contiguous)
// =====================================================================
__global__ void split_kernel(const float* __restrict__ x,
                             __nv_bfloat16* __restrict__ hi,
                             __nv_bfloat16* __restrict__ lo, int n4)
{
    int i = blockIdx.x * blockDim.x + threadIdx.x;
    if (i >= n4) return;
    float4 v = ((const float4*)x)[i];
    __nv_bfloat16 h0 = __float2bfloat16(v.x);
    __nv_bfloat16 h1 = __float2bfloat16(v.y);
    __nv_bfloat16 h2 = __float2bfloat16(v.z);
    __nv_bfloat16 h3 = __float2bfloat16(v.w);
    __nv_bfloat16 l0 = __float2bfloat16(v.x - __bfloat162float(h0));
    __nv_bfloat16 l1 = __float2bfloat16(v.y - __bfloat162float(h1));
    __nv_bfloat16 l2 = __float2bfloat16(v.z - __bfloat162float(h2));
    __nv_bfloat16 l3 = __float2bfloat16(v.w - __bfloat162float(h3));
    __nv_bfloat162* h2p = (__nv_bfloat162*)hi;
    __nv_bfloat162* l2p = (__nv_bfloat162*)lo;
    h2p[2 * i]     = __halves2bfloat162(h0, h1);
    h2p[2 * i + 1] = __halves2bfloat162(h2, h3);
    l2p[2 * i]     = __halves2bfloat162(l0, l1);
    l2p[2 * i + 1] = __halves2bfloat162(l2, l3);
}

// =====================================================================
// split fp32 submatrix (row stride 4096, col offset) -> bf16 hi/lo [., 1024]
// =====================================================================
__global__ void split_strided_kernel(const float* __restrict__ x, int coloff,
                                     __nv_bfloat16* __restrict__ hi,
                                     __nv_bfloat16* __restrict__ lo)
{
    int i = blockIdx.x * blockDim.x + threadIdx.x;
    if (i >= 4096 * 256) return;
    int row = i >> 8, c4 = (i & 255) << 2;
    float4 v = *(const float4*)(x + (size_t)row * 4096 + coloff + c4);
    __nv_bfloat16 h0 = __float2bfloat16(v.x);
    __nv_bfloat16 h1 = __float2bfloat16(v.y);
    __nv_bfloat16 h2 = __float2bfloat16(v.z);
    __nv_bfloat16 h3 = __float2bfloat16(v.w);
    size_t o = (size_t)row * 1024 + c4;
    *(__nv_bfloat162*)(hi + o)     = __halves2bfloat162(h0, h1);
    *(__nv_bfloat162*)(hi + o + 2) = __halves2bfloat162(h2, h3);
    *(__nv_bfloat162*)(lo + o)     = __halves2bfloat162(
        __float2bfloat16(v.x - __bfloat162float(h0)),
        __float2bfloat16(v.y - __bfloat162float(h1)));
    *(__nv_bfloat162*)(lo + o + 2) = __halves2bfloat162(
        __float2bfloat16(v.z - __bfloat162float(h2)),
        __float2bfloat16(v.w - __bfloat162float(h3)));
}

// =====================================================================
// RoPE + scale + bf16 split; input row stride 4096 with column offset
// (still used for K; Q's rope is fused into attention)
// =====================================================================
__global__ void rope_split_kernel(const float* __restrict__ buf, int coloff,
                                  const float* __restrict__ cosb,
                                  const float* __restrict__ sinb,
                                  __nv_bfloat16* __restrict__ oh,
                                  __nv_bfloat16* __restrict__ ol,
                                  int nheads, float scale)
{
    int idx = blockIdx.x * blockDim.x + threadIdx.x;
    int total = 4096 * nheads * 128;
    if (idx >= total) return;
    int j = idx & 127;
    int h = (idx >> 7) % nheads;
    int n = idx / (128 * nheads);
    int t = n & (S_LEN - 1);
    size_t ibase = (size_t)n * 4096 + coloff + h * 256 + j;
    size_t obase = (size_t)n * (nheads * 256) + h * 256 + j;
    float x1 = buf[ibase];
    float x2 = buf[ibase + 128];
    float c = cosb[t * 128 + j];
    float s = sinb[t * 128 + j];
    float y1 = (x1 * c - x2 * s) * scale;
    float y2 = (x1 * s + x2 * c) * scale;
    __nv_bfloat16 h1 = __float2bfloat16(y1);
    __nv_bfloat16 h2v = __float2bfloat16(y2);
    oh[obase]       = h1;
    oh[obase + 128] = h2v;
    ol[obase]       = __float2bfloat16(y1 - __bfloat162float(h1));
    ol[obase + 128] = __float2bfloat16(y2 - __bfloat162float(h2v));
}

// =====================================================================
// HMMA GEMM: 128x128 tile, K-chunk 32, 2-stage, 2 CTAs/SM.
// Single sync per K-iteration (validated R14).
// =====================================================================
#define STAGES 2
#define TILE_B 10240
#define STAGE_B (4 * TILE_B)
#define GEMM_SMEM (STAGES * STAGE_B)   // 81920

__device__ __forceinline__ void issue_stage(
    uint32_t sb, int c, int tid, int m0, int n0, int K,
    const __nv_bfloat16* Ah, const __nv_bfloat16* Al,
    const __nv_bfloat16* Bh, const __nv_bfloat16* Bl)
{
    uint32_t st = sb + (uint32_t)(c & 1) * STAGE_B;
    int k0 = c * 32;
#pragma unroll
    for (int half = 0; half < 2; half++) {
        int idx = tid + half * 256;
        int row = idx >> 2;
        int seg = idx & 3;
        uint32_t so = (uint32_t)(row * 80 + seg * 16);
        size_t ga = (size_t)(m0 + row) * K + k0 + seg * 8;
        size_t gb = (size_t)(n0 + row) * K + k0 + seg * 8;
        cp_async16(st + so,              Ah + ga);
        cp_async16(st + TILE_B + so,     Al + ga);
        cp_async16(st + 2 * TILE_B + so, Bh + gb);
        cp_async16(st + 3 * TILE_B + so, Bl + gb);
    }
    CP_COMMIT();
}

__global__ __launch_bounds__(256, 2) void gemm_hmma(
    const __nv_bfloat16* __restrict__ Ah, const __nv_bfloat16* __restrict__ Al,
    const __nv_bfloat16* __restrict__ Bh, const __nv_bfloat16* __restrict__ Bl,
    float* __restrict__ C, int M, int N, int K)
{
    extern __shared__ __align__(128) char smem[];
    const uint32_t sb = smem_u32(smem);
    const int tid = threadIdx.x;
    const int wid = tid >> 5, lane = tid & 31;
    const int wm = wid >> 2, wn = wid & 3;
    const int m0 = blockIdx.y * 128, n0 = blockIdx.x * 128;

    float acc[4][4][4];
#pragma unroll
    for (int mi = 0; mi < 4; mi++)
#pragma unroll
        for (int ni = 0; ni < 4; ni++)
#pragma unroll
            for (int r = 0; r < 4; r++) acc[mi][ni][r] = 0.f;

    const int NC = K >> 5;
    issue_stage(sb, 0, tid, m0, n0, K, Ah, Al, Bh, Bl);

    const uint32_t aoff = (uint32_t)((wm * 64 + (lane & 15)) * 80 +
                                     (lane >> 4) * 16);
    const uint32_t boff = (uint32_t)((wn * 32 + (lane & 7)) * 80 +
                                     ((lane >> 3) & 1) * 16);

    for (int c = 0; c < NC; c++) {
        CP_WAIT0();
        __syncthreads();
        if (c + 1 < NC)
            issue_stage(sb, c + 1, tid, m0, n0, K, Ah, Al, Bh, Bl);
        const uint32_t st = sb + (uint32_t)(c & 1) * STAGE_B;
        const uint32_t aA = st + aoff;
        const uint32_t aB = st + 2 * TILE_B + boff;

#pragma unroll
        for (int ks = 0; ks < 2; ks++) {
            uint32_t ah[4][4], al[4][4], bh[4][2], bl[4][2];
#pragma unroll
            for (int mi = 0; mi < 4; mi++)
                ldsm_x4(ah[mi], aA + mi * (16 * 80) + ks * 32);
#pragma unroll
            for (int ni = 0; ni < 4; ni++) {
                ldsm_x2(bh[ni], aB + ni * (8 * 80) + ks * 32);
                ldsm_x2(bl[ni], aB + TILE_B + ni * (8 * 80) + ks * 32);
            }
#pragma unroll
            for (int mi = 0; mi < 4; mi++)
#pragma unroll
                for (int ni = 0; ni < 4; ni++) {
                    mma16816(acc[mi][ni], ah[mi], bh[ni]);
                    mma16816(acc[mi][ni], ah[mi], bl[ni]);
                }
#pragma unroll
            for (int mi = 0; mi < 4; mi++)
                ldsm_x4(al[mi], aA + TILE_B + mi * (16 * 80) + ks * 32);
#pragma unroll
            for (int mi = 0; mi < 4; mi++)
#pragma unroll
                for (int ni = 0; ni < 4; ni++)
                    mma16816(acc[mi][ni], al[mi], bh[ni]);
        }
    }

    const int gr = lane >> 2, cn = lane & 3;
#pragma unroll
    for (int mi = 0; mi < 4; mi++) {
        int r = m0 + wm * 64 + mi * 16 + gr;
#pragma unroll
        for (int ni = 0; ni < 4; ni++) {
            int col = n0 + wn * 32 + ni * 8 + cn * 2;
            *(float2*)(C + (size_t)r * N + col) =
                make_float2(acc[mi][ni][0], acc[mi][ni][1]);
            *(float2*)(C + (size_t)(r + 8) * N + col) =
                make_float2(acc[mi][ni][2], acc[mi][ni][3]);
        }
    }
}

// =====================================================================
// HMMA attention: Q rope+scale+split FUSED into prologue (reads fp32
// gqkv directly); K-tile prefetch pipeline (R11/R13); short capexp.
// =====================================================================
#define DP 528
#define PP 144
#define SM_QH 0
#define SM_QL (64 * DP)
#define SM_KH (2 * 64 * DP)
#define SM_KL (3 * 64 * DP)
#define SM_VH (4 * 64 * DP)
#define SM_VL (5 * 64 * DP)
#define SM_PH (6 * 64 * DP)
#define SM_PL (SM_PH + 64 * PP)
#define SM_LS (SM_PL + 64 * PP)
#define ATT_SMEM (SM_LS + 256)

__device__ __forceinline__ float capexp(float s, int ig, int jg) {
    float x = s * INV_CAP;
    x = fminf(fmaxf(x, -15.f), 15.f);
    float e = __expf(2.f * x);
    bool win = (jg <= ig) && (ig - jg < 1024);
    // p = exp(50*tanh(x) - 50) = exp(-100/(e+1))
    return win ? __expf(__fdividef(-100.f, e + 1.f)) : 0.f;
}

__global__ __launch_bounds__(256, 1) void attn_hmma(
    const float* __restrict__ gqkv,
    const float* __restrict__ cosb, const float* __restrict__ sinb,
    const __nv_bfloat16* __restrict__ kh, const __nv_bfloat16* __restrict__ kl,
    const __nv_bfloat16* __restrict__ vh, const __nv_bfloat16* __restrict__ vl,
    float* __restrict__ probs, float* __restrict__ attn_out,
    __nv_bfloat16* __restrict__ gath, __nv_bfloat16* __restrict__ gatl,
    float* __restrict__ linv)
{
    extern __shared__ __align__(128) char smem[];
    const uint32_t sb = smem_u32(smem);
    float* smls = (float*)(smem + SM_LS);
    const int tid = threadIdx.x, wid = tid >> 5, lane = tid & 31;
    const int wm = wid >> 1, wn = wid & 1;
    const int gr = lane >> 2, cn = lane & 3;
    const int q0 = (gridDim.x - 1 - blockIdx.x) * 64;
    const int h = blockIdx.y, b = blockIdx.z;
    const int hkv = h >> 1, bh = b * NH + h;

    const int kstart = max(0, q0 - 1024);

    // prologue: stage fp32 Q tile (into V area) + first K tile, one group
#pragma unroll
    for (int i = 0; i < 16; i++) {
        int idx = tid + i * 256;
        int r = idx >> 6, s = idx & 63;
        size_t g = ((size_t)(b * S_LEN + q0 + r)) * 4096 + h * 256 + s * 4;
        cp_async16(sb + SM_VH + r * 1024 + s * 16, gqkv + g);
    }
#pragma unroll
    for (int i = 0; i < 8; i++) {
        int seg = tid + i * 256;
        int r = seg >> 5, s = seg & 31;
        size_t g = ((size_t)(b * S_LEN + kstart + r)) * 1024 + hkv * 256 + s * 8;
        cp_async16(sb + SM_KH + r * DP + s * 16, kh + g);
        cp_async16(sb + SM_KL + r * DP + s * 16, kl + g);
    }
    CP_COMMIT();
    if (tid < 64) smls[tid] = 0.f;

    float acco[16][4];
#pragma unroll
    for (int i = 0; i < 16; i++)
#pragma unroll
        for (int r = 0; r < 4; r++) acco[i][r] = 0.f;

    const int qg0 = q0 + wm * 16 + gr;
    const int qg1 = qg0 + 8;

    // rope + scale + bf16 split of Q (fp32 staged at SM_VH, 1024B rows)
    CP_WAIT0();
    __syncthreads();
    {
        const float* Qf = (const float*)(smem + SM_VH);
#pragma unroll
        for (int i = 0; i < 32; i++) {
            int idx = tid + i * 256;
            int r = idx >> 7, j = idx & 127;
            int t = q0 + r;
            float x1 = Qf[r * 256 + j];
            float x2 = Qf[r * 256 + j + 128];
            float c = cosb[t * 128 + j];
            float s = sinb[t * 128 + j];
            float y1 = (x1 * c - x2 * s) * QSCALE;
            float y2 = (x1 * s + x2 * c) * QSCALE;
            __nv_bfloat16 h1 = __float2bfloat16(y1);
            __nv_bfloat16 h2 = __float2bfloat16(y2);
            *(__nv_bfloat16*)(smem + SM_QH + r * DP + j * 2) = h1;
            *(__nv_bfloat16*)(smem + SM_QH + r * DP + (j + 128) * 2) = h2;
            *(__nv_bfloat16*)(smem + SM_QL + r * DP + j * 2) =
                __float2bfloat16(y1 - __bfloat162float(h1));
            *(__nv_bfloat16*)(smem + SM_QL + r * DP + (j + 128) * 2) =
                __float2bfloat16(y2 - __bfloat162float(h2));
        }
    }
    // iter-0 loop-top sync publishes QH/QL and releases the Qf staging
    // area (SM_VH) for V's cp.async.

    for (int kt0 = kstart; kt0 <= q0; kt0 += 64) {
        CP_WAIT0();          // K_kt ready (prologue already drained at iter 0)
        __syncthreads();     // QH/QL visible; prior PV reads of V/P done

        // issue V_kt (hides behind S compute)
#pragma unroll
        for (int i = 0; i < 8; i++) {
            int seg = tid + i * 256;
            int r = seg >> 5, s = seg & 31;
            size_t g = ((size_t)(b * S_LEN + kt0 + r)) * 1024 + hkv * 256 + s * 8;
            cp_async16(sb + SM_VH + r * DP + s * 16, vh + g);
            cp_async16(sb + SM_VL + r * DP + s * 16, vl + g);
        }
        CP_COMMIT();

        // ---- S = Q K^T ----
        float sacc[4][4];
#pragma unroll
        for (int ni = 0; ni < 4; ni++)
#pragma unroll
            for (int r = 0; r < 4; r++) sacc[ni][r] = 0.f;

        const uint32_t qa = sb + SM_QH + (wm * 16 + (lane & 15)) * DP +
                            (lane >> 4) * 16;
        const uint32_t kb = sb + SM_KH + (wn * 32 + (lane & 7)) * DP +
                            ((lane >> 3) & 1) * 16;
#pragma unroll 4
        for (int kc = 0; kc < 16; kc++) {
            uint32_t ah[4], al[4], bhf[4][2], blf[4][2];
            ldsm_x4(ah, qa + kc * 32);
            ldsm_x4(al, qa + (SM_QL - SM_QH) + kc * 32);
#pragma unroll
            for (int ni = 0; ni < 4; ni++) {
                ldsm_x2(bhf[ni], kb + ni * (8 * DP) + kc * 32);
                ldsm_x2(blf[ni], kb + (SM_KL - SM_KH) + ni * (8 * DP) + kc * 32);
            }
#pragma unroll
            for (int ni = 0; ni < 4; ni++) {
                mma16816(sacc[ni], ah, bhf[ni]);
                mma16816(sacc[ni], ah, blf[ni]);
                mma16816(sacc[ni], al, bhf[ni]);
            }
        }

        // ---- softcap/exp, P split into smem, row sums ----
        float l0 = 0.f, l1 = 0.f;
#pragma unroll
        for (int ni = 0; ni < 4; ni++) {
            int keyb = kt0 + wn * 32 + ni * 8 + cn * 2;
            float p0 = capexp(sacc[ni][0], qg0, keyb);
            float p1 = capexp(sacc[ni][1], qg0, keyb + 1);
            float p2 = capexp(sacc[ni][2], qg1, keyb);
            float p3 = capexp(sacc[ni][3], qg1, keyb + 1);
            l0 += p0 + p1;
            l1 += p2 + p3;
            __nv_bfloat16 h0 = __float2bfloat16(p0), h1 = __float2bfloat16(p1);
            __nv_bfloat16 h2 = __float2bfloat16(p2), h3 = __float2bfloat16(p3);
            int pcol = (wn * 32 + ni * 8 + cn * 2) * 2;
            int pr0 = (wm * 16 + gr) * PP, pr1 = pr0 + 8 * PP;
            *(__nv_bfloat162*)(smem + SM_PH + pr0 + pcol) = __halves2bfloat162(h0, h1);
            *(__nv_bfloat162*)(smem + SM_PH + pr1 + pcol) = __halves2bfloat162(h2, h3);
            *(__nv_bfloat162*)(smem + SM_PL + pr0 + pcol) = __halves2bfloat162(
                __float2bfloat16(p0 - __bfloat162float(h0)),
                __float2bfloat16(p1 - __bfloat162float(h1)));
            *(__nv_bfloat162*)(smem + SM_PL + pr1 + pcol) = __halves2bfloat162(
                __float2bfloat16(p2 - __bfloat162float(h2)),
                __float2bfloat16(p3 - __bfloat162float(h3)));
        }
        l0 += __shfl_xor_sync(0xffffffffu, l0, 1);
        l0 += __shfl_xor_sync(0xffffffffu, l0, 2);
        l1 += __shfl_xor_sync(0xffffffffu, l1, 1);
        l1 += __shfl_xor_sync(0xffffffffu, l1, 2);
        if (cn == 0) {
            atomicAdd(&smls[wm * 16 + gr], l0);
            atomicAdd(&smls[wm * 16 + gr + 8], l1);
        }

        CP_WAIT0();          // V ready (K_next not yet committed)
        __syncthreads();     // P visible; K-buffer reads done

        // prefetch NEXT K tile (hides behind probs writeback + PV)
        if (kt0 + 64 <= q0) {
#pragma unroll
            for (int i = 0; i < 8; i++) {
                int seg = tid + i * 256;
                int r = seg >> 5, s = seg & 31;
                size_t g = ((size_t)(b * S_LEN + kt0 + 64 + r)) * 1024 +
                           hkv * 256 + s * 8;
                cp_async16(sb + SM_KH + r * DP + s * 16, kh + g);
                cp_async16(sb + SM_KL + r * DP + s * 16, kl + g);
            }
            CP_COMMIT();
        }

        // ---- coalesced probs writeback from smem P (hi+lo) ----
#pragma unroll
        for (int i = 0; i < 4; i++) {
            int idx = tid + i * 256;
            int r = idx >> 4;
            int c4 = (idx & 15) * 4;
            uint2 vh2 = *(const uint2*)(smem + SM_PH + r * PP + c4 * 2);
            uint2 vl2 = *(const uint2*)(smem + SM_PL + r * PP + c4 * 2);
            float2 a0 = __bfloat1622float2(*(__nv_bfloat162*)&vh2.x);
            float2 a1 = __bfloat1622float2(*(__nv_bfloat162*)&vh2.y);
            float2 b0 = __bfloat1622float2(*(__nv_bfloat162*)&vl2.x);
            float2 b1 = __bfloat1622float2(*(__nv_bfloat162*)&vl2.y);
            float4 pv;
            pv.x = a0.x + b0.x; pv.y = a0.y + b0.y;
            pv.z = a1.x + b1.x; pv.w = a1.y + b1.y;
            *(float4*)(probs + ((size_t)bh * S_LEN + q0 + r) * S_LEN + kt0 + c4) = pv;
        }

        // ---- O += P~ V ----
        const uint32_t pa = sb + SM_PH + (wm * 16 + (lane & 15)) * PP +
                            (lane >> 4) * 16;
        const uint32_t vb = sb + SM_VH + (lane & 15) * DP +
                            (wn * 128) * 2 + (lane >> 4) * 16;
#pragma unroll
        for (int kk = 0; kk < 4; kk++) {
            uint32_t ph[4], pl[4];
            ldsm_x4(ph, pa + kk * 32);
            ldsm_x4(pl, pa + (SM_PL - SM_PH) + kk * 32);
#pragma unroll
            for (int nj = 0; nj < 8; nj++) {
                uint32_t vbh[4], vbl[4];
                uint32_t va = vb + kk * (16 * DP) + nj * 32;
                ldsm_x4t(vbh, va);
                ldsm_x4t(vbl, va + (SM_VL - SM_VH));
                mma16816(acco[nj * 2], ph, vbh);
                mma16816(acco[nj * 2], ph, vbl);
                mma16816(acco[nj * 2], pl, vbh);
                mma16816(acco[nj * 2 + 1], ph, vbh + 2);
                mma16816(acco[nj * 2 + 1], ph, vbl + 2);
                mma16816(acco[nj * 2 + 1], pl, vbh + 2);
            }
        }
        // trailing sync elided: next iteration's CP_WAIT0 + __syncthreads
    }
    __syncthreads();

    // ---- final epilogue ----
    if (tid < 64)
        linv[(size_t)bh * S_LEN + q0 + tid] = 1.f / smls[tid];
    float inv0 = 1.f / smls[wm * 16 + gr];
    float inv1 = 1.f / smls[wm * 16 + gr + 8];
#pragma unroll
    for (int ni = 0; ni < 16; ni++) {
        int col = wn * 128 + ni * 8 + cn * 2;
        float o0 = acco[ni][0] * inv0, o1 = acco[ni][1] * inv0;
        float o2 = acco[ni][2] * inv1, o3 = acco[ni][3] * inv1;
        *(float2*)(attn_out + ((size_t)bh * S_LEN + qg0) * 256 + col) =
            make_float2(o0, o1);
        *(float2*)(attn_out + ((size_t)bh * S_LEN + qg1) * 256 + col) =
            make_float2(o2, o3);
        size_t ga0 = ((size_t)(b * S_LEN) + qg0) * 2048 + h * 256 + col;
        size_t ga1 = ((size_t)(b * S_LEN) + qg1) * 2048 + h * 256 + col;
        __nv_bfloat16 h0 = __float2bfloat16(o0), h1 = __float2bfloat16(o1);
        __nv_bfloat16 h2 = __float2bfloat16(o2), h3 = __float2bfloat16(o3);
        *(__nv_bfloat162*)(gath + ga0) = __halves2bfloat162(h0, h1);
        *(__nv_bfloat162*)(gath + ga1) = __halves2bfloat162(h2, h3);
        *(__nv_bfloat162*)(gatl + ga0) = __halves2bfloat162(
            __float2bfloat16(o0 - __bfloat162float(h0)),
            __float2bfloat16(o1 - __bfloat162float(h1)));
        *(__nv_bfloat162*)(gatl + ga1) = __halves2bfloat162(
            __float2bfloat16(o2 - __bfloat162float(h2)),
            __float2bfloat16(o3 - __bfloat162float(h3)));
    }
}

// =====================================================================
// Full-row probs finalize: zero outside the band, scale inside.
// =====================================================================
__global__ void norm_probs_full(float* __restrict__ probs,
                                const float* __restrict__ linv)
{
    int row = blockIdx.x;
    int i = row & (S_LEN - 1);
    float inv = linv[row];
    int lo = max(0, i - 1023);
    float4* p = (float4*)(probs + (size_t)row * S_LEN);
#pragma unroll
    for (int c = (int)threadIdx.x; c < 512; c += 256) {
        int c0 = c << 2;
        float4 v;
        if (c0 + 3 < lo || c0 > i) {
            v = make_float4(0.f, 0.f, 0.f, 0.f);
        } else {
            v = p[c];
            v.x = (c0 >= lo && c0 <= i)         ? v.x * inv : 0.f;
            v.y = (c0 + 1 >= lo && c0 + 1 <= i) ? v.y * inv : 0.f;
            v.z = (c0 + 2 >= lo && c0 + 2 <= i) ? v.z * inv : 0.f;
            v.w = (c0 + 3 >= lo && c0 + 3 <= i) ? v.w * inv : 0.f;
        }
        p[c] = v;
    }
}

// =====================================================================
// Outputs: out[2,2048,2048] @0 | probs @8388608 | attn @75497472
// Stream fork/join (capture-legal, validated R10-R14).
// =====================================================================
extern "C" void kernel_launch(void* const* d_in, const int* in_sizes, int n_in,
                              void* d_out, int out_size)
{
    const float* hs = (const float*)d_in[0];
    const float* fc = (const float*)d_in[1];
    const float* fs = (const float*)d_in[2];
    const float* wq = (const float*)d_in[4];
    const float* wk = (const float*)d_in[5];
    const float* wv = (const float*)d_in[6];
    const float* wo = (const float*)d_in[7];

    float* out   = (float*)d_out;
    float* probs = out + 8388608ull;
    float* attn  = probs + 67108864ull;

    float *gqkv, *glinv;
    cudaGetSymbolAddress((void**)&gqkv, g_qkv);
    cudaGetSymbolAddress((void**)&glinv, g_linv);

    void *hsh, *hsl, *atth, *attl, *wh, *wl, *woh, *wol;
    void *kh, *kl, *vh, *vl;
    cudaGetSymbolAddress(&hsh, g_hs_h);  cudaGetSymbolAddress(&hsl, g_hs_l);
    cudaGetSymbolAddress(&atth, g_att_h); cudaGetSymbolAddress(&attl, g_att_l);
    cudaGetSymbolAddress(&wh, g_w_h);    cudaGetSymbolAddress(&wl, g_w_l);
    cudaGetSymbolAddress(&woh, g_wo_h);  cudaGetSymbolAddress(&wol, g_wo_l);
    cudaGetSymbolAddress(&kh, g_kh);     cudaGetSymbolAddress(&kl, g_kl);
    cudaGetSymbolAddress(&vh, g_vh);     cudaGetSymbolAddress(&vl, g_vl);

    cudaFuncSetAttribute(gemm_hmma,
                         cudaFuncAttributeMaxDynamicSharedMemorySize, GEMM_SMEM);
    cudaFuncSetAttribute(attn_hmma,
                         cudaFuncAttributeMaxDynamicSharedMemorySize, ATT_SMEM);

    static cudaStream_t s1 = nullptr;
    static cudaEvent_t eStart, eW, eWo, eGemm, eP, eAtt, eNorm;
    if (!s1) {
        cudaStreamCreateWithFlags(&s1, cudaStreamNonBlocking);
        cudaEventCreateWithFlags(&eStart, cudaEventDisableTiming);
        cudaEventCreateWithFlags(&eW,     cudaEventDisableTiming);
        cudaEventCreateWithFlags(&eWo,    cudaEventDisableTiming);
        cudaEventCreateWithFlags(&eGemm,  cudaEventDisableTiming);
        cudaEventCreateWithFlags(&eP,     cudaEventDisableTiming);
        cudaEventCreateWithFlags(&eAtt,   cudaEventDisableTiming);
        cudaEventCreateWithFlags(&eNorm,  cudaEventDisableTiming);
    }

    __nv_bfloat16* whb = (__nv_bfloat16*)wh;
    __nv_bfloat16* wlb = (__nv_bfloat16*)wl;

    // fork: side stream handles weight splits while main does hs split
    cudaEventRecord(eStart, 0);
    cudaStreamWaitEvent(s1, eStart, 0);

    split_kernel<<<8192, 256>>>(hs, (__nv_bfloat16*)hsh, (__nv_bfloat16*)hsl,
                                2097152);

    split_kernel<<<4096, 256, 0, s1>>>(wq, whb, wlb, 1048576);
    split_kernel<<<2048, 256, 0, s1>>>(wk, whb + 2048ull * 2048,
                                       wlb + 2048ull * 2048, 524288);
    split_kernel<<<2048, 256, 0, s1>>>(wv, whb + 3072ull * 2048,
                                       wlb + 3072ull * 2048, 524288);
    cudaEventRecord(eW, s1);
    split_kernel<<<4096, 256, 0, s1>>>(wo, (__nv_bfloat16*)woh,
                                       (__nv_bfloat16*)wol, 1048576);
    cudaEventRecord(eWo, s1);

    // main: QKV GEMM
    cudaStreamWaitEvent(0, eW, 0);
    gemm_hmma<<<dim3(32, 32), 256, GEMM_SMEM>>>(
        (const __nv_bfloat16*)hsh, (const __nv_bfloat16*)hsl,
        whb, wlb, gqkv, 4096, 4096, 2048);
    cudaEventRecord(eGemm, 0);

    // fork: rope_k on s1, v split on main (Q rope fused into attention)
    cudaStreamWaitEvent(s1, eGemm, 0);
    rope_split_kernel<<<8192, 256, 0, s1>>>(gqkv, 2048, fc, fs,
                                            (__nv_bfloat16*)kh,
                                            (__nv_bfloat16*)kl, 4, 1.0f);
    cudaEventRecord(eP, s1);

    split_strided_kernel<<<4096, 256>>>(gqkv, 3072, (__nv_bfloat16*)vh,
                                        (__nv_bfloat16*)vl);
    cudaStreamWaitEvent(0, eP, 0);

    // attention on main (Q rope applied in-kernel from gqkv)
    attn_hmma<<<dim3(32, 8, 2), 256, ATT_SMEM>>>(
        gqkv, fc, fs,
        (const __nv_bfloat16*)kh, (const __nv_bfloat16*)kl,
        (const __nv_bfloat16*)vh, (const __nv_bfloat16*)vl,
        probs, attn, (__nv_bfloat16*)atth, (__nv_bfloat16*)attl, glinv);
    cudaEventRecord(eAtt, 0);

    // fork: probs normalize on s1, concurrent with wo GEMM on main
    cudaStreamWaitEvent(s1, eAtt, 0);
    norm_probs_full<<<32768, 256, 0, s1>>>(probs, glinv);
    cudaEventRecord(eNorm, s1);

    cudaStreamWaitEvent(0, eWo, 0);
    gemm_hmma<<<dim3(16, 32), 256, GEMM_SMEM>>>(
        (const __nv_bfloat16*)atth, (const __nv_bfloat16*)attl,
        (const __nv_bfloat16*)woh, (const __nv_bfloat16*)wol, out,
        4096, 2048, 2048);

    // join side stream back into main before returning
    cudaStreamWaitEvent(0, eNorm, 0);
}

// round 16
// speedup vs baseline: 1.1664x; 1.0065x over previous
#include <cuda_runtime.h>
#include <cuda_bf16.h>
#include <math.h>
#include <stdint.h>

#define S_LEN 2048
#define HID   2048
#define NH    8
#define NKV   4
#define HD    256
#define QSCALE 0.0625f       // D^-0.5
#define INV_CAP 0.02f        // 1/50
#define CAP    50.0f

// ---- fp32 scratch ----
__device__ float g_qkv[(size_t)4096 * 4096];   // q cols 0-2047 | k 2048-3071 | (v region unused)
__device__ float g_linv[32768];

// ---- bf16 split scratch ----
__device__ uint4 g_hs_h[(size_t)4096 * 2048 / 8];
__device__ uint4 g_hs_l[(size_t)4096 * 2048 / 8];
__device__ uint4 g_att_h[(size_t)4096 * 2048 / 8];
__device__ uint4 g_att_l[(size_t)4096 * 2048 / 8];
__device__ uint4 g_w_h[(size_t)4096 * 2048 / 8];   // wq rows 0-2047 | wk | wv
__device__ uint4 g_w_l[(size_t)4096 * 2048 / 8];
__device__ uint4 g_wo_h[(size_t)2048 * 2048 / 8];
__device__ uint4 g_wo_l[(size_t)2048 * 2048 / 8];
__device__ uint4 g_kh[(size_t)4096 * 1024 / 8];
__device__ uint4 g_kl[(size_t)4096 * 1024 / 8];
__device__ uint4 g_vh[(size_t)4096 * 1024 / 8];
__device__ uint4 g_vl[(size_t)4096 * 1024 / 8];

// =====================================================================
// helpers
// =====================================================================
__device__ __forceinline__ uint32_t smem_u32(const void* p) {
    uint32_t a;
    asm("{ .reg .u64 t; cvta.to.shared.u64 t, %1; cvt.u32.u64 %0, t; }"
        : "=r"(a) : "l"(p));
    return a;
}
__device__ __forceinline__ void cp_async16(uint32_t saddr, const void* gaddr) {
    asm volatile("cp.async.cg.shared.global [%0], [%1], 16;"
                 :: "r"(saddr), "l"(gaddr) : "memory");
}
#define CP_COMMIT() asm volatile("cp.async.commit_group;" ::: "memory")
#define CP_WAIT1()  asm volatile("cp.async.wait_group 1;" ::: "memory")
#define CP_WAIT0()  asm volatile("cp.async.wait_group 0;" ::: "memory")

__device__ __forceinline__ void ldsm_x4(uint32_t* r, uint32_t addr) {
    asm volatile("ldmatrix.sync.aligned.m8n8.x4.shared.b16 {%0,%1,%2,%3}, [%4];"
                 : "=r"(r[0]), "=r"(r[1]), "=r"(r[2]), "=r"(r[3]) : "r"(addr));
}
__device__ __forceinline__ void ldsm_x4t(uint32_t* r, uint32_t addr) {
    asm volatile("ldmatrix.sync.aligned.m8n8.x4.trans.shared.b16 {%0,%1,%2,%3}, [%4];"
                 : "=r"(r[0]), "=r"(r[1]), "=r"(r[2]), "=r"(r[3]) : "r"(addr));
}
__device__ __forceinline__ void ldsm_x2(uint32_t* r, uint32_t addr) {
    asm volatile("ldmatrix.sync.aligned.m8n8.x2.shared.b16 {%0,%1}, [%2];"
                 : "=r"(r[0]), "=r"(r[1]) : "r"(addr));
}
__device__ __forceinline__ void mma16816(float* c, const uint32_t* a,
                                         const uint32_t* b) {
    asm volatile(
        "mma.sync.aligned.m16n8k16.row.col.f32.bf16.bf16.f32 "
        "{%0,%1,%2,%3}, {%4,%5,%6,%7}, {%8,%9}, {%0,%1,%2,%3};"
        : "+f"(c[0]), "+f"(c[1]), "+f"(c[2]), "+f"(c[3])
        : "r"(a[0]), "r"(a[1]), "r"(a[2]), "r"(a[3]), "r"(b[0]), "r"(b[1]));
}

// =====================================================================
// split fp32 -> (hi, lo) bf16  (contiguous)
// =====================================================================
__global__ void split_kernel(const float* __restrict__ x,
                             __nv_bfloat16* __restrict__ hi,
                             __nv_bfloat16* __restrict__ lo, int n4)
{
    int i = blockIdx.x * blockDim.x + threadIdx.x;
    if (i >= n4) return;
    float4 v = ((const float4*)x)[i];
    __nv_bfloat16 h0 = __float2bfloat16(v.x);
    __nv_bfloat16 h1 = __float2bfloat16(v.y);
    __nv_bfloat16 h2 = __float2bfloat16(v.z);
    __nv_bfloat16 h3 = __float2bfloat16(v.w);
    __nv_bfloat16 l0 = __float2bfloat16(v.x - __bfloat162float(h0));
    __nv_bfloat16 l1 = __float2bfloat16(v.y - __bfloat162float(h1));
    __nv_bfloat16 l2 = __float2bfloat16(v.z - __bfloat162float(h2));
    __nv_bfloat16 l3 = __float2bfloat16(v.w - __bfloat162float(h3));
    __nv_bfloat162* h2p = (__nv_bfloat162*)hi;
    __nv_bfloat162* l2p = (__nv_bfloat162*)lo;
    h2p[2 * i]     = __halves2bfloat162(h0, h1);
    h2p[2 * i + 1] = __halves2bfloat162(h2, h3);
    l2p[2 * i]     = __halves2bfloat162(l0, l1);
    l2p[2 * i + 1] = __halves2bfloat162(l2, l3);
}

// =====================================================================
// RoPE + scale + bf16 split; input row stride 4096 with column offset
// (used for K; Q's rope is fused into attention)
// =====================================================================
__global__ void rope_split_kernel(const float* __restrict__ buf, int coloff,
                                  const float* __restrict__ cosb,
                                  const float* __restrict__ sinb,
                                  __nv_bfloat16* __restrict__ oh,
                                  __nv_bfloat16* __restrict__ ol,
                                  int nheads, float scale)
{
    int idx = blockIdx.x * blockDim.x + threadIdx.x;
    int total = 4096 * nheads * 128;
    if (idx >= total) return;
    int j = idx & 127;
    int h = (idx >> 7) % nheads;
    int n = idx / (128 * nheads);
    int t = n & (S_LEN - 1);
    size_t ibase = (size_t)n * 4096 + coloff + h * 256 + j;
    size_t obase = (size_t)n * (nheads * 256) + h * 256 + j;
    float x1 = buf[ibase];
    float x2 = buf[ibase + 128];
    float c = cosb[t * 128 + j];
    float s = sinb[t * 128 + j];
    float y1 = (x1 * c - x2 * s) * scale;
    float y2 = (x1 * s + x2 * c) * scale;
    __nv_bfloat16 h1 = __float2bfloat16(y1);
    __nv_bfloat16 h2v = __float2bfloat16(y2);
    oh[obase]       = h1;
    oh[obase + 128] = h2v;
    ol[obase]       = __float2bfloat16(y1 - __bfloat162float(h1));
    ol[obase + 128] = __float2bfloat16(y2 - __bfloat162float(h2v));
}

// =====================================================================
// HMMA GEMM: 128x128 tile, K-chunk 32, 2-stage, 2 CTAs/SM.
// Single sync per K-iteration (R14). Epilogue: CTAs with n0 >= voff
// write bf16 hi/lo split (V path, row stride 1024) instead of fp32 C.
// =====================================================================
#define STAGES 2
#define TILE_B 10240
#define STAGE_B (4 * TILE_B)
#define GEMM_SMEM (STAGES * STAGE_B)   // 81920

__device__ __forceinline__ void issue_stage(
    uint32_t sb, int c, int tid, int m0, int n0, int K,
    const __nv_bfloat16* Ah, const __nv_bfloat16* Al,
    const __nv_bfloat16* Bh, const __nv_bfloat16* Bl)
{
    uint32_t st = sb + (uint32_t)(c & 1) * STAGE_B;
    int k0 = c * 32;
#pragma unroll
    for (int half = 0; half < 2; half++) {
        int idx = tid + half * 256;
        int row = idx >> 2;
        int seg = idx & 3;
        uint32_t so = (uint32_t)(row * 80 + seg * 16);
        size_t ga = (size_t)(m0 + row) * K + k0 + seg * 8;
        size_t gb = (size_t)(n0 + row) * K + k0 + seg * 8;
        cp_async16(st + so,              Ah + ga);
        cp_async16(st + TILE_B + so,     Al + ga);
        cp_async16(st + 2 * TILE_B + so, Bh + gb);
        cp_async16(st + 3 * TILE_B + so, Bl + gb);
    }
    CP_COMMIT();
}

__global__ __launch_bounds__(256, 2) void gemm_hmma(
    const __nv_bfloat16* __restrict__ Ah, const __nv_bfloat16* __restrict__ Al,
    const __nv_bfloat16* __restrict__ Bh, const __nv_bfloat16* __restrict__ Bl,
    float* __restrict__ C, int M, int N, int K,
    __nv_bfloat16* __restrict__ Vh, __nv_bfloat16* __restrict__ Vl, int voff)
{
    extern __shared__ __align__(128) char smem[];
    const uint32_t sb = smem_u32(smem);
    const int tid = threadIdx.x;
    const int wid = tid >> 5, lane = tid & 31;
    const int wm = wid >> 2, wn = wid & 3;
    const int m0 = blockIdx.y * 128, n0 = blockIdx.x * 128;

    float acc[4][4][4];
#pragma unroll
    for (int mi = 0; mi < 4; mi++)
#pragma unroll
        for (int ni = 0; ni < 4; ni++)
#pragma unroll
            for (int r = 0; r < 4; r++) acc[mi][ni][r] = 0.f;

    const int NC = K >> 5;
    issue_stage(sb, 0, tid, m0, n0, K, Ah, Al, Bh, Bl);

    const uint32_t aoff = (uint32_t)((wm * 64 + (lane & 15)) * 80 +
                                     (lane >> 4) * 16);
    const uint32_t boff = (uint32_t)((wn * 32 + (lane & 7)) * 80 +
                                     ((lane >> 3) & 1) * 16);

    for (int c = 0; c < NC; c++) {
        CP_WAIT0();
        __syncthreads();
        if (c + 1 < NC)
            issue_stage(sb, c + 1, tid, m0, n0, K, Ah, Al, Bh, Bl);
        const uint32_t st = sb + (uint32_t)(c & 1) * STAGE_B;
        const uint32_t aA = st + aoff;
        const uint32_t aB = st + 2 * TILE_B + boff;

#pragma unroll
        for (int ks = 0; ks < 2; ks++) {
            uint32_t ah[4][4], al[4][4], bh[4][2], bl[4][2];
#pragma unroll
            for (int mi = 0; mi < 4; mi++)
                ldsm_x4(ah[mi], aA + mi * (16 * 80) + ks * 32);
#pragma unroll
            for (int ni = 0; ni < 4; ni++) {
                ldsm_x2(bh[ni], aB + ni * (8 * 80) + ks * 32);
                ldsm_x2(bl[ni], aB + TILE_B + ni * (8 * 80) + ks * 32);
            }
#pragma unroll
            for (int mi = 0; mi < 4; mi++)
#pragma unroll
                for (int ni = 0; ni < 4; ni++) {
                    mma16816(acc[mi][ni], ah[mi], bh[ni]);
                    mma16816(acc[mi][ni], ah[mi], bl[ni]);
                }
#pragma unroll
            for (int mi = 0; mi < 4; mi++)
                ldsm_x4(al[mi], aA + TILE_B + mi * (16 * 80) + ks * 32);
#pragma unroll
            for (int mi = 0; mi < 4; mi++)
#pragma unroll
                for (int ni = 0; ni < 4; ni++)
                    mma16816(acc[mi][ni], al[mi], bh[ni]);
        }
    }

    const int gr = lane >> 2, cn = lane & 3;
    if (n0 >= voff) {
        // V columns: write bf16 hi/lo split directly (row stride 1024)
#pragma unroll
        for (int mi = 0; mi < 4; mi++) {
            int r = m0 + wm * 64 + mi * 16 + gr;
#pragma unroll
            for (int ni = 0; ni < 4; ni++) {
                int vcol = n0 - voff + wn * 32 + ni * 8 + cn * 2;
                float a0 = acc[mi][ni][0], a1 = acc[mi][ni][1];
                float a2 = acc[mi][ni][2], a3 = acc[mi][ni][3];
                __nv_bfloat16 h0 = __float2bfloat16(a0);
                __nv_bfloat16 h1 = __float2bfloat16(a1);
                __nv_bfloat16 h2 = __float2bfloat16(a2);
                __nv_bfloat16 h3 = __float2bfloat16(a3);
                *(__nv_bfloat162*)(Vh + (size_t)r * 1024 + vcol) =
                    __halves2bfloat162(h0, h1);
                *(__nv_bfloat162*)(Vl + (size_t)r * 1024 + vcol) =
                    __halves2bfloat162(
                        __float2bfloat16(a0 - __bfloat162float(h0)),
                        __float2bfloat16(a1 - __bfloat162float(h1)));
                *(__nv_bfloat162*)(Vh + (size_t)(r + 8) * 1024 + vcol) =
                    __halves2bfloat162(h2, h3);
                *(__nv_bfloat162*)(Vl + (size_t)(r + 8) * 1024 + vcol) =
                    __halves2bfloat162(
                        __float2bfloat16(a2 - __bfloat162float(h2)),
                        __float2bfloat16(a3 - __bfloat162float(h3)));
            }
        }
    } else {
#pragma unroll
        for (int mi = 0; mi < 4; mi++) {
            int r = m0 + wm * 64 + mi * 16 + gr;
#pragma unroll
            for (int ni = 0; ni < 4; ni++) {
                int col = n0 + wn * 32 + ni * 8 + cn * 2;
                *(float2*)(C + (size_t)r * N + col) =
                    make_float2(acc[mi][ni][0], acc[mi][ni][1]);
                *(float2*)(C + (size_t)(r + 8) * N + col) =
                    make_float2(acc[mi][ni][2], acc[mi][ni][3]);
            }
        }
    }
}

// =====================================================================
// HMMA attention: Q rope+scale+split fused prologue (R15);
// K-tile prefetch pipeline; short capexp.
// =====================================================================
#define DP 528
#define PP 144
#define SM_QH 0
#define SM_QL (64 * DP)
#define SM_KH (2 * 64 * DP)
#define SM_KL (3 * 64 * DP)
#define SM_VH (4 * 64 * DP)
#define SM_VL (5 * 64 * DP)
#define SM_PH (6 * 64 * DP)
#define SM_PL (SM_PH + 64 * PP)
#define SM_LS (SM_PL + 64 * PP)
#define ATT_SMEM (SM_LS + 256)

__device__ __forceinline__ float capexp(float s, int ig, int jg) {
    float x = s * INV_CAP;
    x = fminf(fmaxf(x, -15.f), 15.f);
    float e = __expf(2.f * x);
    bool win = (jg <= ig) && (ig - jg < 1024);
    return win ? __expf(__fdividef(-100.f, e + 1.f)) : 0.f;
}

__global__ __launch_bounds__(256, 1) void attn_hmma(
    const float* __restrict__ gqkv,
    const float* __restrict__ cosb, const float* __restrict__ sinb,
    const __nv_bfloat16* __restrict__ kh, const __nv_bfloat16* __restrict__ kl,
    const __nv_bfloat16* __restrict__ vh, const __nv_bfloat16* __restrict__ vl,
    float* __restrict__ probs, float* __restrict__ attn_out,
    __nv_bfloat16* __restrict__ gath, __nv_bfloat16* __restrict__ gatl,
    float* __restrict__ linv)
{
    extern __shared__ __align__(128) char smem[];
    const uint32_t sb = smem_u32(smem);
    float* smls = (float*)(smem + SM_LS);
    const int tid = threadIdx.x, wid = tid >> 5, lane = tid & 31;
    const int wm = wid >> 1, wn = wid & 1;
    const int gr = lane >> 2, cn = lane & 3;
    const int q0 = (gridDim.x - 1 - blockIdx.x) * 64;
    const int h = blockIdx.y, b = blockIdx.z;
    const int hkv = h >> 1, bh = b * NH + h;

    const int kstart = max(0, q0 - 1024);

    // prologue: stage fp32 Q tile (into V area) + first K tile, one group
#pragma unroll
    for (int i = 0; i < 16; i++) {
        int idx = tid + i * 256;
        int r = idx >> 6, s = idx & 63;
        size_t g = ((size_t)(b * S_LEN + q0 + r)) * 4096 + h * 256 + s * 4;
        cp_async16(sb + SM_VH + r * 1024 + s * 16, gqkv + g);
    }
#pragma unroll
    for (int i = 0; i < 8; i++) {
        int seg = tid + i * 256;
        int r = seg >> 5, s = seg & 31;
        size_t g = ((size_t)(b * S_LEN + kstart + r)) * 1024 + hkv * 256 + s * 8;
        cp_async16(sb + SM_KH + r * DP + s * 16, kh + g);
        cp_async16(sb + SM_KL + r * DP + s * 16, kl + g);
    }
    CP_COMMIT();
    if (tid < 64) smls[tid] = 0.f;

    float acco[16][4];
#pragma unroll
    for (int i = 0; i < 16; i++)
#pragma unroll
        for (int r = 0; r < 4; r++) acco[i][r] = 0.f;

    const int qg0 = q0 + wm * 16 + gr;
    const int qg1 = qg0 + 8;

    // rope + scale + bf16 split of Q (fp32 staged at SM_VH, 1024B rows)
    CP_WAIT0();
    __syncthreads();
    {
        const float* Qf = (const float*)(smem + SM_VH);
#pragma unroll
        for (int i = 0; i < 32; i++) {
            int idx = tid + i * 256;
            int r = idx >> 7, j = idx & 127;
            int t = q0 + r;
            float x1 = Qf[r * 256 + j];
            float x2 = Qf[r * 256 + j + 128];
            float c = cosb[t * 128 + j];
            float s = sinb[t * 128 + j];
            float y1 = (x1 * c - x2 * s) * QSCALE;
            float y2 = (x1 * s + x2 * c) * QSCALE;
            __nv_bfloat16 h1 = __float2bfloat16(y1);
            __nv_bfloat16 h2 = __float2bfloat16(y2);
            *(__nv_bfloat16*)(smem + SM_QH + r * DP + j * 2) = h1;
            *(__nv_bfloat16*)(smem + SM_QH + r * DP + (j + 128) * 2) = h2;
            *(__nv_bfloat16*)(smem + SM_QL + r * DP + j * 2) =
                __float2bfloat16(y1 - __bfloat162float(h1));
            *(__nv_bfloat16*)(smem + SM_QL + r * DP + (j + 128) * 2) =
                __float2bfloat16(y2 - __bfloat162float(h2));
        }
    }

    for (int kt0 = kstart; kt0 <= q0; kt0 += 64) {
        CP_WAIT0();
        __syncthreads();

        // issue V_kt (hides behind S compute)
#pragma unroll
        for (int i = 0; i < 8; i++) {
            int seg = tid + i * 256;
            int r = seg >> 5, s = seg & 31;
            size_t g = ((size_t)(b * S_LEN + kt0 + r)) * 1024 + hkv * 256 + s * 8;
            cp_async16(sb + SM_VH + r * DP + s * 16, vh + g);
            cp_async16(sb + SM_VL + r * DP + s * 16, vl + g);
        }
        CP_COMMIT();

        // ---- S = Q K^T ----
        float sacc[4][4];
#pragma unroll
        for (int ni = 0; ni < 4; ni++)
#pragma unroll
            for (int r = 0; r < 4; r++) sacc[ni][r] = 0.f;

        const uint32_t qa = sb + SM_QH + (wm * 16 + (lane & 15)) * DP +
                            (lane >> 4) * 16;
        const uint32_t kb = sb + SM_KH + (wn * 32 + (lane & 7)) * DP +
                            ((lane >> 3) & 1) * 16;
#pragma unroll 4
        for (int kc = 0; kc < 16; kc++) {
            uint32_t ah[4], al[4], bhf[4][2], blf[4][2];
            ldsm_x4(ah, qa + kc * 32);
            ldsm_x4(al, qa + (SM_QL - SM_QH) + kc * 32);
#pragma unroll
            for (int ni = 0; ni < 4; ni++) {
                ldsm_x2(bhf[ni], kb + ni * (8 * DP) + kc * 32);
                ldsm_x2(blf[ni], kb + (SM_KL - SM_KH) + ni * (8 * DP) + kc * 32);
            }
#pragma unroll
            for (int ni = 0; ni < 4; ni++) {
                mma16816(sacc[ni], ah, bhf[ni]);
                mma16816(sacc[ni], ah, blf[ni]);
                mma16816(sacc[ni], al, bhf[ni]);
            }
        }

        // ---- softcap/exp, P split into smem, row sums ----
        float l0 = 0.f, l1 = 0.f;
#pragma unroll
        for (int ni = 0; ni < 4; ni++) {
            int keyb = kt0 + wn * 32 + ni * 8 + cn * 2;
            float p0 = capexp(sacc[ni][0], qg0, keyb);
            float p1 = capexp(sacc[ni][1], qg0, keyb + 1);
            float p2 = capexp(sacc[ni][2], qg1, keyb);
            float p3 = capexp(sacc[ni][3], qg1, keyb + 1);
            l0 += p0 + p1;
            l1 += p2 + p3;
            __nv_bfloat16 h0 = __float2bfloat16(p0), h1 = __float2bfloat16(p1);
            __nv_bfloat16 h2 = __float2bfloat16(p2), h3 = __float2bfloat16(p3);
            int pcol = (wn * 32 + ni * 8 + cn * 2) * 2;
            int pr0 = (wm * 16 + gr) * PP, pr1 = pr0 + 8 * PP;
            *(__nv_bfloat162*)(smem + SM_PH + pr0 + pcol) = __halves2bfloat162(h0, h1);
            *(__nv_bfloat162*)(smem + SM_PH + pr1 + pcol) = __halves2bfloat162(h2, h3);
            *(__nv_bfloat162*)(smem + SM_PL + pr0 + pcol) = __halves2bfloat162(
                __float2bfloat16(p0 - __bfloat162float(h0)),
                __float2bfloat16(p1 - __bfloat162float(h1)));
            *(__nv_bfloat162*)(smem + SM_PL + pr1 + pcol) = __halves2bfloat162(
                __float2bfloat16(p2 - __bfloat162float(h2)),
                __float2bfloat16(p3 - __bfloat162float(h3)));
        }
        l0 += __shfl_xor_sync(0xffffffffu, l0, 1);
        l0 += __shfl_xor_sync(0xffffffffu, l0, 2);
        l1 += __shfl_xor_sync(0xffffffffu, l1, 1);
        l1 += __shfl_xor_sync(0xffffffffu, l1, 2);
        if (cn == 0) {
            atomicAdd(&smls[wm * 16 + gr], l0);
            atomicAdd(&smls[wm * 16 + gr + 8], l1);
        }

        CP_WAIT0();
        __syncthreads();

        // prefetch NEXT K tile (hides behind probs writeback + PV)
        if (kt0 + 64 <= q0) {
#pragma unroll
            for (int i = 0; i < 8; i++) {
                int seg = tid + i * 256;
                int r = seg >> 5, s = seg & 31;
                size_t g = ((size_t)(b * S_LEN + kt0 + 64 + r)) * 1024 +
                           hkv * 256 + s * 8;
                cp_async16(sb + SM_KH + r * DP + s * 16, kh + g);
                cp_async16(sb + SM_KL + r * DP + s * 16, kl + g);
            }
            CP_COMMIT();
        }

        // ---- coalesced probs writeback from smem P (hi+lo) ----
#pragma unroll
        for (int i = 0; i < 4; i++) {
            int idx = tid + i * 256;
            int r = idx >> 4;
            int c4 = (idx & 15) * 4;
            uint2 vh2 = *(const uint2*)(smem + SM_PH + r * PP + c4 * 2);
            uint2 vl2 = *(const uint2*)(smem + SM_PL + r * PP + c4 * 2);
            float2 a0 = __bfloat1622float2(*(__nv_bfloat162*)&vh2.x);
            float2 a1 = __bfloat1622float2(*(__nv_bfloat162*)&vh2.y);
            float2 b0 = __bfloat1622float2(*(__nv_bfloat162*)&vl2.x);
            float2 b1 = __bfloat1622float2(*(__nv_bfloat162*)&vl2.y);
            float4 pv;
            pv.x = a0.x + b0.x; pv.y = a0.y + b0.y;
            pv.z = a1.x + b1.x; pv.w = a1.y + b1.y;
            *(float4*)(probs + ((size_t)bh * S_LEN + q0 + r) * S_LEN + kt0 + c4) = pv;
        }

        // ---- O += P~ V ----
        const uint32_t pa = sb + SM_PH + (wm * 16 + (lane & 15)) * PP +
                            (lane >> 4) * 16;
        const uint32_t vb = sb + SM_VH + (lane & 15) * DP +
                            (wn * 128) * 2 + (lane >> 4) * 16;
#pragma unroll
        for (int kk = 0; kk < 4; kk++) {
            uint32_t ph[4], pl[4];
            ldsm_x4(ph, pa + kk * 32);
            ldsm_x4(pl, pa + (SM_PL - SM_PH) + kk * 32);
#pragma unroll
            for (int nj = 0; nj < 8; nj++) {
                uint32_t vbh[4], vbl[4];
                uint32_t va = vb + kk * (16 * DP) + nj * 32;
                ldsm_x4t(vbh, va);
                ldsm_x4t(vbl, va + (SM_VL - SM_VH));
                mma16816(acco[nj * 2], ph, vbh);
                mma16816(acco[nj * 2], ph, vbl);
                mma16816(acco[nj * 2], pl, vbh);
                mma16816(acco[nj * 2 + 1], ph, vbh + 2);
                mma16816(acco[nj * 2 + 1], ph, vbl + 2);
                mma16816(acco[nj * 2 + 1], pl, vbh + 2);
            }
        }
    }
    __syncthreads();

    // ---- final epilogue ----
    if (tid < 64)
        linv[(size_t)bh * S_LEN + q0 + tid] = 1.f / smls[tid];
    float inv0 = 1.f / smls[wm * 16 + gr];
    float inv1 = 1.f / smls[wm * 16 + gr + 8];
#pragma unroll
    for (int ni = 0; ni < 16; ni++) {
        int col = wn * 128 + ni * 8 + cn * 2;
        float o0 = acco[ni][0] * inv0, o1 = acco[ni][1] * inv0;
        float o2 = acco[ni][2] * inv1, o3 = acco[ni][3] * inv1;
        *(float2*)(attn_out + ((size_t)bh * S_LEN + qg0) * 256 + col) =
            make_float2(o0, o1);
        *(float2*)(attn_out + ((size_t)bh * S_LEN + qg1) * 256 + col) =
            make_float2(o2, o3);
        size_t ga0 = ((size_t)(b * S_LEN) + qg0) * 2048 + h * 256 + col;
        size_t ga1 = ((size_t)(b * S_LEN) + qg1) * 2048 + h * 256 + col;
        __nv_bfloat16 h0 = __float2bfloat16(o0), h1 = __float2bfloat16(o1);
        __nv_bfloat16 h2 = __float2bfloat16(o2), h3 = __float2bfloat16(o3);
        *(__nv_bfloat162*)(gath + ga0) = __halves2bfloat162(h0, h1);
        *(__nv_bfloat162*)(gath + ga1) = __halves2bfloat162(h2, h3);
        *(__nv_bfloat162*)(gatl + ga0) = __halves2bfloat162(
            __float2bfloat16(o0 - __bfloat162float(h0)),
            __float2bfloat16(o1 - __bfloat162float(h1)));
        *(__nv_bfloat162*)(gatl + ga1) = __halves2bfloat162(
            __float2bfloat16(o2 - __bfloat162float(h2)),
            __float2bfloat16(o3 - __bfloat162float(h3)));
    }
}

// =====================================================================
// Full-row probs finalize: zero outside the band, scale inside.
// =====================================================================
__global__ void norm_probs_full(float* __restrict__ probs,
                                const float* __restrict__ linv)
{
    int row = blockIdx.x;
    int i = row & (S_LEN - 1);
    float inv = linv[row];
    int lo = max(0, i - 1023);
    float4* p = (float4*)(probs + (size_t)row * S_LEN);
#pragma unroll
    for (int c = (int)threadIdx.x; c < 512; c += 256) {
        int c0 = c << 2;
        float4 v;
        if (c0 + 3 < lo || c0 > i) {
            v = make_float4(0.f, 0.f, 0.f, 0.f);
        } else {
            v = p[c];
            v.x = (c0 >= lo && c0 <= i)         ? v.x * inv : 0.f;
            v.y = (c0 + 1 >= lo && c0 + 1 <= i) ? v.y * inv : 0.f;
            v.z = (c0 + 2 >= lo && c0 + 2 <= i) ? v.z * inv : 0.f;
            v.w = (c0 + 3 >= lo && c0 + 3 <= i) ? v.w * inv : 0.f;
        }
        p[c] = v;
    }
}

// =====================================================================
// Outputs: out[2,2048,2048] @0 | probs @8388608 | attn @75497472
// Stream fork/join (capture-legal, validated R10-R15).
// =====================================================================
extern "C" void kernel_launch(void* const* d_in, const int* in_sizes, int n_in,
                              void* d_out, int out_size)
{
    const float* hs = (const float*)d_in[0];
    const float* fc = (const float*)d_in[1];
    const float* fs = (const float*)d_in[2];
    const float* wq = (const float*)d_in[4];
    const float* wk = (const float*)d_in[5];
    const float* wv = (const float*)d_in[6];
    const float* wo = (const float*)d_in[7];

    float* out   = (float*)d_out;
    float* probs = out + 8388608ull;
    float* attn  = probs + 67108864ull;

    float *gqkv, *glinv;
    cudaGetSymbolAddress((void**)&gqkv, g_qkv);
    cudaGetSymbolAddress((void**)&glinv, g_linv);

    void *hsh, *hsl, *atth, *attl, *wh, *wl, *woh, *wol;
    void *kh, *kl, *vh, *vl;
    cudaGetSymbolAddress(&hsh, g_hs_h);  cudaGetSymbolAddress(&hsl, g_hs_l);
    cudaGetSymbolAddress(&atth, g_att_h); cudaGetSymbolAddress(&attl, g_att_l);
    cudaGetSymbolAddress(&wh, g_w_h);    cudaGetSymbolAddress(&wl, g_w_l);
    cudaGetSymbolAddress(&woh, g_wo_h);  cudaGetSymbolAddress(&wol, g_wo_l);
    cudaGetSymbolAddress(&kh, g_kh);     cudaGetSymbolAddress(&kl, g_kl);
    cudaGetSymbolAddress(&vh, g_vh);     cudaGetSymbolAddress(&vl, g_vl);

    cudaFuncSetAttribute(gemm_hmma,
                         cudaFuncAttributeMaxDynamicSharedMemorySize, GEMM_SMEM);
    cudaFuncSetAttribute(attn_hmma,
                         cudaFuncAttributeMaxDynamicSharedMemorySize, ATT_SMEM);

    static cudaStream_t s1 = nullptr;
    static cudaEvent_t eStart, eW, eWo, eGemm, eP, eAtt, eNorm;
    if (!s1) {
        cudaStreamCreateWithFlags(&s1, cudaStreamNonBlocking);
        cudaEventCreateWithFlags(&eStart, cudaEventDisableTiming);
        cudaEventCreateWithFlags(&eW,     cudaEventDisableTiming);
        cudaEventCreateWithFlags(&eWo,    cudaEventDisableTiming);
        cudaEventCreateWithFlags(&eGemm,  cudaEventDisableTiming);
        cudaEventCreateWithFlags(&eP,     cudaEventDisableTiming);
        cudaEventCreateWithFlags(&eAtt,   cudaEventDisableTiming);
        cudaEventCreateWithFlags(&eNorm,  cudaEventDisableTiming);
    }

    __nv_bfloat16* whb = (__nv_bfloat16*)wh;
    __nv_bfloat16* wlb = (__nv_bfloat16*)wl;

    // fork: side stream handles weight splits while main does hs split
    cudaEventRecord(eStart, 0);
    cudaStreamWaitEvent(s1, eStart, 0);

    split_kernel<<<8192, 256>>>(hs, (__nv_bfloat16*)hsh, (__nv_bfloat16*)hsl,
                                2097152);

    split_kernel<<<4096, 256, 0, s1>>>(wq, whb, wlb, 1048576);
    split_kernel<<<2048, 256, 0, s1>>>(wk, whb + 2048ull * 2048,
                                       wlb + 2048ull * 2048, 524288);
    split_kernel<<<2048, 256, 0, s1>>>(wv, whb + 3072ull * 2048,
                                       wlb + 3072ull * 2048, 524288);
    cudaEventRecord(eW, s1);
    split_kernel<<<4096, 256, 0, s1>>>(wo, (__nv_bfloat16*)woh,
                                       (__nv_bfloat16*)wol, 1048576);
    cudaEventRecord(eWo, s1);

    // main: QKV GEMM (V columns split to bf16 in-epilogue)
    cudaStreamWaitEvent(0, eW, 0);
    gemm_hmma<<<dim3(32, 32), 256, GEMM_SMEM>>>(
        (const __nv_bfloat16*)hsh, (const __nv_bfloat16*)hsl,
        whb, wlb, gqkv, 4096, 4096, 2048,
        (__nv_bfloat16*)vh, (__nv_bfloat16*)vl, 3072);
    cudaEventRecord(eGemm, 0);

    // fork: rope_k on s1 (Q rope fused into attention; V split fused in GEMM)
    cudaStreamWaitEvent(s1, eGemm, 0);
    rope_split_kernel<<<8192, 256, 0, s1>>>(gqkv, 2048, fc, fs,
                                            (__nv_bfloat16*)kh,
                                            (__nv_bfloat16*)kl, 4, 1.0f);
    cudaEventRecord(eP, s1);

    cudaStreamWaitEvent(0, eP, 0);

    // attention on main (Q rope applied in-kernel from gqkv)
    attn_hmma<<<dim3(32, 8, 2), 256, ATT_SMEM>>>(
        gqkv, fc, fs,
        (const __nv_bfloat16*)kh, (const __nv_bfloat16*)kl,
        (const __nv_bfloat16*)vh, (const __nv_bfloat16*)vl,
        probs, attn, (__nv_bfloat16*)atth, (__nv_bfloat16*)attl, glinv);
    cudaEventRecord(eAtt, 0);

    // fork: probs normalize on s1, concurrent with wo GEMM on main
    cudaStreamWaitEvent(s1, eAtt, 0);
    norm_probs_full<<<32768, 256, 0, s1>>>(probs, glinv);
    cudaEventRecord(eNorm, s1);

    cudaStreamWaitEvent(0, eWo, 0);
    gemm_hmma<<<dim3(16, 32), 256, GEMM_SMEM>>>(
        (const __nv_bfloat16*)atth, (const __nv_bfloat16*)attl,
        (const __nv_bfloat16*)woh, (const __nv_bfloat16*)wol, out,
        4096, 2048, 2048,
        nullptr, nullptr, 2048);

    // join side stream back into main before returning
    cudaStreamWaitEvent(0, eNorm, 0);
}